// round 3
// baseline (speedup 1.0000x reference)
#include <cuda_runtime.h>
#include <math.h>

// ---------------- problem constants ----------------
#define Bb   2
#define Nn   8192
#define Ee   1024
#define Hh   16
#define Dd   64
#define Cc   128
#define NCk  64          // chunks per sequence
#define Mm   (Bb*Nn)     // 16384 rows

// ---------------- device scratch (no allocs allowed) ----------------
__device__ float g_q[(size_t)Mm*Ee];
__device__ float g_k[(size_t)Mm*Ee];
__device__ float g_v[(size_t)Mm*Ee];
__device__ float g_o[(size_t)Mm*Ee];
__device__ float g_u[(size_t)Mm*Ee];
__device__ float g_A [(size_t)Bb*Hh*NCk*Dd*Dd];   // per-chunk kv contributions
__device__ float g_kv[(size_t)Bb*Hh*NCk*Dd*Dd];   // kv prefix state per chunk
__device__ float g_g1[(size_t)Mm*Dd];

__device__ __forceinline__ float head_slope(int h) {
    // ALiBi slopes for H=16: 2^{-0.5(h+1)}, scaled by (1 - 0/11 + 1e-5)
    return exp2f(-0.5f * (float)(h + 1)) * 1.00001f;
}

__device__ __forceinline__ float maybe_silu(float v, int act) {
    return act ? v / (1.0f + expf(-v)) : v;
}

// ============================================================
// QKV fused SGEMM: z selects (Wq->g_q, Wk->g_k, Wv->g_v), silu applied.
// C[M,N] = silu(A[M,K] @ W[K,N]), 128x128 tile, BK=8
// 256 threads, 8x8 microtile, double-buffered smem
// ============================================================
__global__ __launch_bounds__(256) void sgemm_qkv(
    const float* __restrict__ A,
    const float* __restrict__ Wq, const float* __restrict__ Wk,
    const float* __restrict__ Wv)
{
    __shared__ float As[2][8][128];   // transposed: As[k][m]
    __shared__ float Bs[2][8][128];

    const float* W = (blockIdx.z == 0) ? Wq : (blockIdx.z == 1) ? Wk : Wv;
    float* C = (blockIdx.z == 0) ? g_q : (blockIdx.z == 1) ? g_k : g_v;
    const int N = Ee, K = Ee;

    const int tid  = threadIdx.x;
    const int tx   = tid & 15;
    const int ty   = tid >> 4;
    const int brow = blockIdx.y * 128;
    const int bcol = blockIdx.x * 128;

    const int arow = tid >> 1;
    const int acol = (tid & 1) * 4;
    const int bkr  = tid >> 5;
    const int bcl  = (tid & 31) * 4;

    const float* Ap = A + (size_t)(brow + arow) * K + acol;
    const float* Bp = W + (size_t)bkr * N + bcol + bcl;

    float4 ar = *(const float4*)Ap;
    float4 br = *(const float4*)Bp;
    As[0][acol + 0][arow] = ar.x;
    As[0][acol + 1][arow] = ar.y;
    As[0][acol + 2][arow] = ar.z;
    As[0][acol + 3][arow] = ar.w;
    *(float4*)&Bs[0][bkr][bcl] = br;
    __syncthreads();

    float acc[8][8];
#pragma unroll
    for (int i = 0; i < 8; i++)
#pragma unroll
        for (int j = 0; j < 8; j++) acc[i][j] = 0.0f;

    int buf = 0;
    for (int k0 = 8; k0 <= K; k0 += 8) {
        if (k0 < K) {
            ar = *(const float4*)(Ap + k0);
            br = *(const float4*)(Bp + (size_t)k0 * N);
        }
#pragma unroll
        for (int kk = 0; kk < 8; kk++) {
            float af[8], bf[8];
            *(float4*)&af[0] = *(float4*)&As[buf][kk][ty * 8];
            *(float4*)&af[4] = *(float4*)&As[buf][kk][ty * 8 + 4];
            *(float4*)&bf[0] = *(float4*)&Bs[buf][kk][tx * 8];
            *(float4*)&bf[4] = *(float4*)&Bs[buf][kk][tx * 8 + 4];
#pragma unroll
            for (int i = 0; i < 8; i++)
#pragma unroll
                for (int j = 0; j < 8; j++)
                    acc[i][j] = fmaf(af[i], bf[j], acc[i][j]);
        }
        if (k0 < K) {
            buf ^= 1;
            As[buf][acol + 0][arow] = ar.x;
            As[buf][acol + 1][arow] = ar.y;
            As[buf][acol + 2][arow] = ar.z;
            As[buf][acol + 3][arow] = ar.w;
            *(float4*)&Bs[buf][bkr][bcl] = br;
            __syncthreads();
        }
    }

#pragma unroll
    for (int i = 0; i < 8; i++) {
        float* Cp = C + (size_t)(brow + ty * 8 + i) * N + bcol + tx * 8;
#pragma unroll
        for (int j0 = 0; j0 < 8; j0 += 4) {
            float4 o;
            o.x = maybe_silu(acc[i][j0 + 0], 1);
            o.y = maybe_silu(acc[i][j0 + 1], 1);
            o.z = maybe_silu(acc[i][j0 + 2], 1);
            o.w = maybe_silu(acc[i][j0 + 3], 1);
            *(float4*)(Cp + j0) = o;
        }
    }
}

// ============================================================
// Output SGEMM: out = g_u @ Wo (no activation), same tiling
// ============================================================
__global__ __launch_bounds__(256) void sgemm_out(
    const float* __restrict__ W, float* __restrict__ C)
{
    __shared__ float As[2][8][128];
    __shared__ float Bs[2][8][128];

    const float* A = g_u;
    const int N = Ee, K = Ee;

    const int tid  = threadIdx.x;
    const int tx   = tid & 15;
    const int ty   = tid >> 4;
    const int brow = blockIdx.y * 128;
    const int bcol = blockIdx.x * 128;

    const int arow = tid >> 1;
    const int acol = (tid & 1) * 4;
    const int bkr  = tid >> 5;
    const int bcl  = (tid & 31) * 4;

    const float* Ap = A + (size_t)(brow + arow) * K + acol;
    const float* Bp = W + (size_t)bkr * N + bcol + bcl;

    float4 ar = *(const float4*)Ap;
    float4 br = *(const float4*)Bp;
    As[0][acol + 0][arow] = ar.x;
    As[0][acol + 1][arow] = ar.y;
    As[0][acol + 2][arow] = ar.z;
    As[0][acol + 3][arow] = ar.w;
    *(float4*)&Bs[0][bkr][bcl] = br;
    __syncthreads();

    float acc[8][8];
#pragma unroll
    for (int i = 0; i < 8; i++)
#pragma unroll
        for (int j = 0; j < 8; j++) acc[i][j] = 0.0f;

    int buf = 0;
    for (int k0 = 8; k0 <= K; k0 += 8) {
        if (k0 < K) {
            ar = *(const float4*)(Ap + k0);
            br = *(const float4*)(Bp + (size_t)k0 * N);
        }
#pragma unroll
        for (int kk = 0; kk < 8; kk++) {
            float af[8], bf[8];
            *(float4*)&af[0] = *(float4*)&As[buf][kk][ty * 8];
            *(float4*)&af[4] = *(float4*)&As[buf][kk][ty * 8 + 4];
            *(float4*)&bf[0] = *(float4*)&Bs[buf][kk][tx * 8];
            *(float4*)&bf[4] = *(float4*)&Bs[buf][kk][tx * 8 + 4];
#pragma unroll
            for (int i = 0; i < 8; i++)
#pragma unroll
                for (int j = 0; j < 8; j++)
                    acc[i][j] = fmaf(af[i], bf[j], acc[i][j]);
        }
        if (k0 < K) {
            buf ^= 1;
            As[buf][acol + 0][arow] = ar.x;
            As[buf][acol + 1][arow] = ar.y;
            As[buf][acol + 2][arow] = ar.z;
            As[buf][acol + 3][arow] = ar.w;
            *(float4*)&Bs[buf][bkr][bcl] = br;
            __syncthreads();
        }
    }

#pragma unroll
    for (int i = 0; i < 8; i++) {
        float* Cp = C + (size_t)(brow + ty * 8 + i) * N + bcol + tx * 8;
#pragma unroll
        for (int j0 = 0; j0 < 8; j0 += 4) {
            float4 o;
            o.x = acc[i][j0 + 0];
            o.y = acc[i][j0 + 1];
            o.z = acc[i][j0 + 2];
            o.w = acc[i][j0 + 3];
            *(float4*)(Cp + j0) = o;
        }
    }
}

// ============================================================
// g1 = x @ Wg1 : [16384,64], K=1024.  128x64 tile, 8x4 microtile
// ============================================================
__global__ __launch_bounds__(256) void sgemm_g1(
    const float* __restrict__ A, const float* __restrict__ W)
{
    __shared__ float As[2][8][128];
    __shared__ float Bs[2][8][64];

    const int tid  = threadIdx.x;
    const int tx   = tid & 15;
    const int ty   = tid >> 4;
    const int brow = blockIdx.x * 128;
    const int K = Ee;

    const int arow = tid >> 1;
    const int acol = (tid & 1) * 4;
    const float* Ap = A + (size_t)(brow + arow) * K + acol;

    const int bkr = tid >> 4;       // 0..15 (only tid<128 used)
    const int bcl = (tid & 15) * 4;
    const float* Bp = W + (size_t)bkr * Dd + bcl;

    float4 ar = *(const float4*)Ap;
    float4 br = make_float4(0, 0, 0, 0);
    if (tid < 128) br = *(const float4*)Bp;
    As[0][acol + 0][arow] = ar.x;
    As[0][acol + 1][arow] = ar.y;
    As[0][acol + 2][arow] = ar.z;
    As[0][acol + 3][arow] = ar.w;
    if (tid < 128) *(float4*)&Bs[0][bkr][bcl] = br;
    __syncthreads();

    float acc[8][4];
#pragma unroll
    for (int i = 0; i < 8; i++)
#pragma unroll
        for (int j = 0; j < 4; j++) acc[i][j] = 0.0f;

    int buf = 0;
    for (int k0 = 8; k0 <= K; k0 += 8) {
        if (k0 < K) {
            ar = *(const float4*)(Ap + k0);
            if (tid < 128) br = *(const float4*)(Bp + (size_t)k0 * Dd);
        }
#pragma unroll
        for (int kk = 0; kk < 8; kk++) {
            float af[8], bf[4];
            *(float4*)&af[0] = *(float4*)&As[buf][kk][ty * 8];
            *(float4*)&af[4] = *(float4*)&As[buf][kk][ty * 8 + 4];
            *(float4*)&bf[0] = *(float4*)&Bs[buf][kk][tx * 4];
#pragma unroll
            for (int i = 0; i < 8; i++)
#pragma unroll
                for (int j = 0; j < 4; j++)
                    acc[i][j] = fmaf(af[i], bf[j], acc[i][j]);
        }
        if (k0 < K) {
            buf ^= 1;
            As[buf][acol + 0][arow] = ar.x;
            As[buf][acol + 1][arow] = ar.y;
            As[buf][acol + 2][arow] = ar.z;
            As[buf][acol + 3][arow] = ar.w;
            if (tid < 128) *(float4*)&Bs[buf][bkr][bcl] = br;
            __syncthreads();
        }
    }

#pragma unroll
    for (int i = 0; i < 8; i++) {
        float4 o;
        o.x = acc[i][0]; o.y = acc[i][1]; o.z = acc[i][2]; o.w = acc[i][3];
        *(float4*)(g_g1 + (size_t)(brow + ty * 8 + i) * Dd + tx * 4) = o;
    }
}

// ============================================================
// Intra-chunk attention + per-chunk kv contribution A_c
// grid (NC, H, B), 256 threads, dynamic smem
// ============================================================
#define SM_QT   0
#define SM_KT   (64*132)
#define SM_VS   (2*64*132)
#define SM_SS   (2*64*132 + 128*68)
#define SM_LAM  (2*64*132 + 128*68 + 128*129)
#define SMEM_INTRA_FLOATS (2*64*132 + 128*68 + 128*129 + 128)

__global__ __launch_bounds__(256) void attn_intra(
    const float* __restrict__ q, const float* __restrict__ k,
    const float* __restrict__ v)
{
    extern __shared__ float sm[];
    float* qT  = sm + SM_QT;   // [64][132]  (d-major, transposed)
    float* kT  = sm + SM_KT;   // [64][132]
    float* vs  = sm + SM_VS;   // [128][68]  (row-major)
    float* Ss  = sm + SM_SS;   // [128][129]
    float* lamk = sm + SM_LAM; // [128]

    const int c = blockIdx.x, h = blockIdx.y, b = blockIdx.z;
    const int tid = threadIdx.x;
    const float s = head_slope(h);
    const size_t base = ((size_t)b * Nn + (size_t)c * Cc) * Ee + (size_t)h * Dd;

    // ---- load q,k,v tiles (128 x 64) ----
#pragma unroll
    for (int t = 0; t < 8; t++) {
        int e = tid + t * 256;     // float4 index 0..2047
        int row = e >> 4;
        int d4 = (e & 15) * 4;
        const size_t g = base + (size_t)row * Ee + d4;
        float4 qv = *(const float4*)(q + g);
        qT[(d4 + 0) * 132 + row] = qv.x;
        qT[(d4 + 1) * 132 + row] = qv.y;
        qT[(d4 + 2) * 132 + row] = qv.z;
        qT[(d4 + 3) * 132 + row] = qv.w;
        float4 kv4 = *(const float4*)(k + g);
        kT[(d4 + 0) * 132 + row] = kv4.x;
        kT[(d4 + 1) * 132 + row] = kv4.y;
        kT[(d4 + 2) * 132 + row] = kv4.z;
        kT[(d4 + 3) * 132 + row] = kv4.w;
        *(float4*)&vs[row * 68 + d4] = *(const float4*)(v + g);
    }
    if (tid < 128) lamk[tid] = expf(-s * (float)(Cc - 1 - tid));
    __syncthreads();

    const int tx = tid & 15, ty = tid >> 4;

    // ---- S = q k^T (128x128), 8x8 per thread ----
    float acc[8][8];
#pragma unroll
    for (int i = 0; i < 8; i++)
#pragma unroll
        for (int j = 0; j < 8; j++) acc[i][j] = 0.0f;

    for (int d = 0; d < 64; d++) {
        float af[8], bf[8];
        *(float4*)&af[0] = *(float4*)&qT[d * 132 + ty * 8];
        *(float4*)&af[4] = *(float4*)&qT[d * 132 + ty * 8 + 4];
        *(float4*)&bf[0] = *(float4*)&kT[d * 132 + tx * 8];
        *(float4*)&bf[4] = *(float4*)&kT[d * 132 + tx * 8 + 4];
#pragma unroll
        for (int i = 0; i < 8; i++)
#pragma unroll
            for (int j = 0; j < 8; j++)
                acc[i][j] = fmaf(af[i], bf[j], acc[i][j]);
    }
    // mask + decay, write to smem
#pragma unroll
    for (int ii = 0; ii < 8; ii++) {
        int i = ty * 8 + ii;
#pragma unroll
        for (int jj = 0; jj < 8; jj++) {
            int j = tx * 8 + jj;
            float val = 0.0f;
            if (i >= j) val = acc[ii][jj] * expf(-s * (float)(i - j));
            Ss[i * 129 + j] = val;
        }
    }
    __syncthreads();

    // ---- O_intra = S @ v  (128x64), 8x4 per thread ----
    float oc[8][4];
#pragma unroll
    for (int i = 0; i < 8; i++)
#pragma unroll
        for (int j = 0; j < 4; j++) oc[i][j] = 0.0f;

    for (int j = 0; j < 128; j++) {
        float bv[4];
        *(float4*)bv = *(float4*)&vs[j * 68 + tx * 4];
#pragma unroll
        for (int ii = 0; ii < 8; ii++) {
            float a = Ss[(ty * 8 + ii) * 129 + j];
#pragma unroll
            for (int dd = 0; dd < 4; dd++)
                oc[ii][dd] = fmaf(a, bv[dd], oc[ii][dd]);
        }
    }
#pragma unroll
    for (int ii = 0; ii < 8; ii++) {
        float4 o;
        o.x = oc[ii][0]; o.y = oc[ii][1]; o.z = oc[ii][2]; o.w = oc[ii][3];
        *(float4*)(g_o + base + (size_t)(ty * 8 + ii) * Ee + tx * 4) = o;
    }

    // ---- A_c[d][e] = sum_j k[j,d]*lamk[j]*v[j,e]  (64x64), 4x4 per thread ----
    float ac[4][4];
#pragma unroll
    for (int i = 0; i < 4; i++)
#pragma unroll
        for (int j = 0; j < 4; j++) ac[i][j] = 0.0f;

    const int dr = ty * 4;
    for (int j = 0; j < 128; j++) {
        float lam = lamk[j];
        float bv[4];
        *(float4*)bv = *(float4*)&vs[j * 68 + tx * 4];
#pragma unroll
        for (int i = 0; i < 4; i++) {
            float a = kT[(dr + i) * 132 + j] * lam;
#pragma unroll
            for (int e2 = 0; e2 < 4; e2++)
                ac[i][e2] = fmaf(a, bv[e2], ac[i][e2]);
        }
    }
    float* Ab = g_A + ((((size_t)b * Hh + h) * NCk + c) * (Dd * Dd));
#pragma unroll
    for (int i = 0; i < 4; i++) {
        float4 o;
        o.x = ac[i][0]; o.y = ac[i][1]; o.z = ac[i][2]; o.w = ac[i][3];
        *(float4*)&Ab[(dr + i) * Dd + tx * 4] = o;
    }
}

// ============================================================
// kv prefix scan: 32 blocks, each scans 64 chunks of 64x64 state
// ============================================================
__global__ __launch_bounds__(256) void kv_scan()
{
    const int h = blockIdx.x, b = blockIdx.y;
    const int tid = threadIdx.x;
    const float s = head_slope(h);
    const float lamc = expf(-s * (float)Cc);
    float kv[16];
#pragma unroll
    for (int i = 0; i < 16; i++) kv[i] = 0.0f;

    const size_t base = (((size_t)b * Hh + h) * NCk) * (Dd * Dd);
    for (int c = 0; c < NCk; c++) {
        const size_t off = base + (size_t)c * (Dd * Dd);
#pragma unroll
        for (int i = 0; i < 16; i++) {
            g_kv[off + tid + i * 256] = kv[i];                       // prefix (pre-chunk state)
            kv[i] = lamc * kv[i] + g_A[off + tid + i * 256];
        }
    }
}

// ============================================================
// Inter-chunk: o += lam_q[i] * (q @ kv_prefix)
// grid (NC, H, B), 256 threads, dynamic smem (qs 128x68 + kvs 64x68)
// ============================================================
#define SMEM_INTER_FLOATS (128*68 + 64*68)

__global__ __launch_bounds__(256) void attn_inter(const float* __restrict__ q)
{
    extern __shared__ float sm[];
    float* qs  = sm;             // [128][68]
    float* kvs = sm + 128 * 68;  // [64][68]

    const int c = blockIdx.x, h = blockIdx.y, b = blockIdx.z;
    const int tid = threadIdx.x;
    const float s = head_slope(h);
    const size_t base = ((size_t)b * Nn + (size_t)c * Cc) * Ee + (size_t)h * Dd;

#pragma unroll
    for (int t = 0; t < 8; t++) {
        int e = tid + t * 256;
        int row = e >> 4;
        int d4 = (e & 15) * 4;
        *(float4*)&qs[row * 68 + d4] = *(const float4*)(q + base + (size_t)row * Ee + d4);
    }
    const float* kvp = g_kv + (((size_t)b * Hh + h) * NCk + c) * (Dd * Dd);
#pragma unroll
    for (int t = 0; t < 4; t++) {
        int e = tid + t * 256;
        int row = e >> 4;
        int d4 = (e & 15) * 4;
        *(float4*)&kvs[row * 68 + d4] = *(const float4*)(kvp + row * Dd + d4);
    }
    __syncthreads();

    const int tx = tid & 15, ty = tid >> 4;
    float oc[8][4];
#pragma unroll
    for (int i = 0; i < 8; i++)
#pragma unroll
        for (int j = 0; j < 4; j++) oc[i][j] = 0.0f;

    for (int e2 = 0; e2 < 64; e2++) {
        float bv[4];
        *(float4*)bv = *(float4*)&kvs[e2 * 68 + tx * 4];
#pragma unroll
        for (int ii = 0; ii < 8; ii++) {
            float a = qs[(ty * 8 + ii) * 68 + e2];
#pragma unroll
            for (int dd = 0; dd < 4; dd++)
                oc[ii][dd] = fmaf(a, bv[dd], oc[ii][dd]);
        }
    }
#pragma unroll
    for (int ii = 0; ii < 8; ii++) {
        int i = ty * 8 + ii;
        float lamq = expf(-s * (float)(i + 1));
        float* op = g_o + base + (size_t)i * Ee + tx * 4;
        float4 prev = *(float4*)op;
        prev.x = fmaf(lamq, oc[ii][0], prev.x);
        prev.y = fmaf(lamq, oc[ii][1], prev.y);
        prev.z = fmaf(lamq, oc[ii][2], prev.z);
        prev.w = fmaf(lamq, oc[ii][3], prev.w);
        *(float4*)op = prev;
    }
}

// ============================================================
// LayerNorm + gate (g1 @ Wg2 -> sigmoid) + multiply -> g_u
// 8 rows per block, 256 threads
// ============================================================
__global__ __launch_bounds__(256) void ln_gate(
    const float* __restrict__ gamma, const float* __restrict__ beta,
    const float* __restrict__ Wg2)
{
    __shared__ float os[8 * 1024];
    __shared__ float g1s[8 * 64];
    __shared__ float wsum[8], wsq[8];
    __shared__ float mu_s[8], rs_s[8];

    const int tid = threadIdx.x;
    const size_t row0 = (size_t)blockIdx.x * 8;

#pragma unroll
    for (int t = 0; t < 8; t++) {
        int e = tid + t * 256;     // float4 idx 0..2047
        int r = e >> 8;
        int c4 = (e & 255) * 4;
        *(float4*)&os[r * 1024 + c4] = *(const float4*)(g_o + (row0 + r) * 1024 + c4);
    }
    if (tid < 128) {
        int r = tid >> 4;
        int c4 = (tid & 15) * 4;
        *(float4*)&g1s[r * 64 + c4] = *(const float4*)(g_g1 + (row0 + r) * 64 + c4);
    }
    __syncthreads();

    const int lane = tid & 31, wid = tid >> 5;

    // pass 1: mean
    for (int r = 0; r < 8; r++) {
        float sum = 0.0f;
#pragma unroll
        for (int t = 0; t < 4; t++) sum += os[r * 1024 + tid + t * 256];
#pragma unroll
        for (int o = 16; o; o >>= 1) sum += __shfl_xor_sync(0xffffffffu, sum, o);
        if (lane == 0) wsum[wid] = sum;
        __syncthreads();
        if (tid == 0) {
            float S = 0.0f;
            for (int w = 0; w < 8; w++) S += wsum[w];
            mu_s[r] = S * (1.0f / 1024.0f);
        }
        __syncthreads();
    }
    // pass 2: variance (two-pass for stability)
    for (int r = 0; r < 8; r++) {
        float mu = mu_s[r];
        float sq = 0.0f;
#pragma unroll
        for (int t = 0; t < 4; t++) {
            float d = os[r * 1024 + tid + t * 256] - mu;
            sq = fmaf(d, d, sq);
        }
#pragma unroll
        for (int o = 16; o; o >>= 1) sq += __shfl_xor_sync(0xffffffffu, sq, o);
        if (lane == 0) wsq[wid] = sq;
        __syncthreads();
        if (tid == 0) {
            float Q = 0.0f;
            for (int w = 0; w < 8; w++) Q += wsq[w];
            rs_s[r] = rsqrtf(Q * (1.0f / 1024.0f) + 1e-5f);
        }
        __syncthreads();
    }

    // outputs: warp w handles row w, 4-wide chunks
    const int r = wid;
    const int cbase = lane * 4;
    const float mu = mu_s[r];
    const float rs = rs_s[r];
#pragma unroll
    for (int t = 0; t < 8; t++) {
        int col = cbase + t * 128;
        float4 ov = *(float4*)&os[r * 1024 + col];
        float4 gd = make_float4(0, 0, 0, 0);
        for (int kk = 0; kk < 64; kk++) {
            float gk = g1s[r * 64 + kk];
            float4 w = *(const float4*)(Wg2 + (size_t)kk * 1024 + col);
            gd.x = fmaf(gk, w.x, gd.x);
            gd.y = fmaf(gk, w.y, gd.y);
            gd.z = fmaf(gk, w.z, gd.z);
            gd.w = fmaf(gk, w.w, gd.w);
        }
        float4 gm = *(const float4*)(gamma + col);
        float4 bt = *(const float4*)(beta + col);
        float4 u;
        u.x = (fmaf((ov.x - mu) * rs, gm.x, bt.x)) * (1.0f / (1.0f + expf(-gd.x)));
        u.y = (fmaf((ov.y - mu) * rs, gm.y, bt.y)) * (1.0f / (1.0f + expf(-gd.y)));
        u.z = (fmaf((ov.z - mu) * rs, gm.z, bt.z)) * (1.0f / (1.0f + expf(-gd.z)));
        u.w = (fmaf((ov.w - mu) * rs, gm.w, bt.w)) * (1.0f / (1.0f + expf(-gd.w)));
        *(float4*)(g_u + (row0 + r) * 1024 + col) = u;
    }
}

// ============================================================
// host launch
// ============================================================
extern "C" void kernel_launch(void* const* d_in, const int* in_sizes, int n_in,
                              void* d_out, int out_size)
{
    const float* x     = (const float*)d_in[0];
    const float* Wq    = (const float*)d_in[1];
    const float* Wk    = (const float*)d_in[2];
    const float* Wv    = (const float*)d_in[3];
    const float* Wo    = (const float*)d_in[4];
    const float* gamma = (const float*)d_in[5];
    const float* beta  = (const float*)d_in[6];
    const float* Wg1   = (const float*)d_in[7];
    const float* Wg2   = (const float*)d_in[8];
    float* out = (float*)d_out;

    static bool init_done = false;
    static float *qp, *kp, *vp;
    if (!init_done) {
        cudaGetSymbolAddress((void**)&qp, g_q);
        cudaGetSymbolAddress((void**)&kp, g_k);
        cudaGetSymbolAddress((void**)&vp, g_v);
        cudaFuncSetAttribute(attn_intra, cudaFuncAttributeMaxDynamicSharedMemorySize,
                             SMEM_INTRA_FLOATS * (int)sizeof(float));
        cudaFuncSetAttribute(attn_inter, cudaFuncAttributeMaxDynamicSharedMemorySize,
                             SMEM_INTER_FLOATS * (int)sizeof(float));
        init_done = true;
    }

    const int smem_intra = SMEM_INTRA_FLOATS * (int)sizeof(float);
    const int smem_inter = SMEM_INTER_FLOATS * (int)sizeof(float);

    dim3 blk(256);

    sgemm_qkv<<<dim3(Ee / 128, Mm / 128, 3), blk>>>(x, Wq, Wk, Wv);
    sgemm_g1<<<Mm / 128, blk>>>(x, Wg1);

    attn_intra<<<dim3(NCk, Hh, Bb), blk, smem_intra>>>(qp, kp, vp);
    kv_scan<<<dim3(Hh, Bb), blk>>>();
    attn_inter<<<dim3(NCk, Hh, Bb), blk, smem_inter>>>(qp);

    ln_gate<<<Mm / 8, blk>>>(gamma, beta, Wg2);

    sgemm_out<<<dim3(Ee / 128, Mm / 128), blk>>>(Wo, out);
}

// round 4
// speedup vs baseline: 2.2520x; 2.2520x over previous
#include <cuda_runtime.h>
#include <math.h>
#include <stdint.h>

// ---------------- problem constants ----------------
#define Bb   2
#define Nn   8192
#define Ee   1024
#define Hh   16
#define Dd   64
#define Cc   128
#define NCk  64          // chunks per sequence
#define Mm   (Bb*Nn)     // 16384 rows

// ---------------- device scratch (no allocs allowed) ----------------
__device__ float g_q[(size_t)Mm*Ee];
__device__ float g_k[(size_t)Mm*Ee];
__device__ float g_v[(size_t)Mm*Ee];
__device__ float g_o[(size_t)Mm*Ee];
__device__ float g_u[(size_t)Mm*Ee];
__device__ float g_A [(size_t)Bb*Hh*NCk*Dd*Dd];   // per-chunk kv contributions
__device__ float g_kv[(size_t)Bb*Hh*NCk*Dd*Dd];   // kv prefix state per chunk
__device__ float g_g1[(size_t)Mm*Dd];

__device__ __forceinline__ float head_slope(int h) {
    return exp2f(-0.5f * (float)(h + 1)) * 1.00001f;
}

__device__ __forceinline__ float silu_f(float v) {
    return v / (1.0f + expf(-v));
}

__device__ __forceinline__ uint32_t f2tf32(float x) {
    uint32_t r;
    asm("cvt.rna.tf32.f32 %0, %1;" : "=r"(r) : "f"(x));
    return r;
}

// ============================================================
// tf32 tensor-core GEMM core: C[128,128] tile = A[M,K]@W[K,N]
// 256 thr = 8 warps (4 m-groups x 2 n-groups), warp tile 32x64,
// m16n8k8 tf32 mma, BK=16 double-buffered.
// As[m][20] pad: A-frag LDS conflict-free (g*20 mod 32 distinct).
// Bs[k][136] pad: B-frag LDS conflict-free (t*136 mod 32 = 8t).
// ============================================================
#define PAD_A 20
#define PAD_B 136

__device__ __forceinline__ void mma_tf32(
    float c[4], const uint32_t a[4], const uint32_t b[2])
{
    asm volatile(
        "mma.sync.aligned.m16n8k8.row.col.f32.tf32.tf32.f32 "
        "{%0,%1,%2,%3}, {%4,%5,%6,%7}, {%8,%9}, {%0,%1,%2,%3};"
        : "+f"(c[0]), "+f"(c[1]), "+f"(c[2]), "+f"(c[3])
        : "r"(a[0]), "r"(a[1]), "r"(a[2]), "r"(a[3]),
          "r"(b[0]), "r"(b[1]));
}

__device__ void gemm_tf32_core(
    const float* __restrict__ A, const float* __restrict__ W,
    float* __restrict__ C, int brow, int bcol, int act)
{
    __shared__ uint32_t As[2][128][PAD_A];
    __shared__ uint32_t Bs[2][16][PAD_B];

    const int K = Ee, N = Ee;
    const int tid  = threadIdx.x;
    const int wid  = tid >> 5;
    const int lane = tid & 31;
    const int g = lane >> 2, t = lane & 3;
    const int wm = (wid & 3) * 32;
    const int wn = (wid >> 2) * 64;

    // G2S index plan (2 float4 per thread per tensor per buffer)
    const int am0 = tid >> 2;            // 0..63
    const int ac0 = (tid & 3) * 4;       // k sub-offset
    const int am1 = am0 + 64;
    const int bk0 = tid >> 5;            // 0..7
    const int bk1 = bk0 + 8;
    const int bn0 = (tid & 31) * 4;

    const float* Ap0 = A + (size_t)(brow + am0) * K + ac0;
    const float* Ap1 = A + (size_t)(brow + am1) * K + ac0;
    const float* Bp0 = W + (size_t)bk0 * N + bcol + bn0;
    const float* Bp1 = W + (size_t)bk1 * N + bcol + bn0;

    float acc[2][8][4];
#pragma unroll
    for (int mi = 0; mi < 2; mi++)
#pragma unroll
        for (int ni = 0; ni < 8; ni++)
#pragma unroll
            for (int j = 0; j < 4; j++) acc[mi][ni][j] = 0.0f;

    // preload buffer 0
    {
        float4 a0 = *(const float4*)Ap0;
        float4 a1 = *(const float4*)Ap1;
        float4 b0 = *(const float4*)Bp0;
        float4 b1 = *(const float4*)Bp1;
        uint4 u;
        u.x = f2tf32(a0.x); u.y = f2tf32(a0.y); u.z = f2tf32(a0.z); u.w = f2tf32(a0.w);
        *(uint4*)&As[0][am0][ac0] = u;
        u.x = f2tf32(a1.x); u.y = f2tf32(a1.y); u.z = f2tf32(a1.z); u.w = f2tf32(a1.w);
        *(uint4*)&As[0][am1][ac0] = u;
        u.x = f2tf32(b0.x); u.y = f2tf32(b0.y); u.z = f2tf32(b0.z); u.w = f2tf32(b0.w);
        *(uint4*)&Bs[0][bk0][bn0] = u;
        u.x = f2tf32(b1.x); u.y = f2tf32(b1.y); u.z = f2tf32(b1.z); u.w = f2tf32(b1.w);
        *(uint4*)&Bs[0][bk1][bn0] = u;
    }
    __syncthreads();

    int buf = 0;
    for (int k0 = 16; k0 <= K; k0 += 16) {
        float4 pa0, pa1, pb0, pb1;
        if (k0 < K) {
            pa0 = *(const float4*)(Ap0 + k0);
            pa1 = *(const float4*)(Ap1 + k0);
            pb0 = *(const float4*)(Bp0 + (size_t)k0 * N);
            pb1 = *(const float4*)(Bp1 + (size_t)k0 * N);
        }

#pragma unroll
        for (int kk = 0; kk < 16; kk += 8) {
            uint32_t afr[2][4], bfr[8][2];
#pragma unroll
            for (int mi = 0; mi < 2; mi++) {
                int m = wm + mi * 16 + g;
                afr[mi][0] = As[buf][m][kk + t];
                afr[mi][1] = As[buf][m + 8][kk + t];
                afr[mi][2] = As[buf][m][kk + t + 4];
                afr[mi][3] = As[buf][m + 8][kk + t + 4];
            }
#pragma unroll
            for (int ni = 0; ni < 8; ni++) {
                int n = wn + ni * 8 + g;
                bfr[ni][0] = Bs[buf][kk + t][n];
                bfr[ni][1] = Bs[buf][kk + t + 4][n];
            }
#pragma unroll
            for (int mi = 0; mi < 2; mi++)
#pragma unroll
                for (int ni = 0; ni < 8; ni++)
                    mma_tf32(acc[mi][ni], afr[mi], bfr[ni]);
        }

        if (k0 < K) {
            int nb = buf ^ 1;
            uint4 u;
            u.x = f2tf32(pa0.x); u.y = f2tf32(pa0.y); u.z = f2tf32(pa0.z); u.w = f2tf32(pa0.w);
            *(uint4*)&As[nb][am0][ac0] = u;
            u.x = f2tf32(pa1.x); u.y = f2tf32(pa1.y); u.z = f2tf32(pa1.z); u.w = f2tf32(pa1.w);
            *(uint4*)&As[nb][am1][ac0] = u;
            u.x = f2tf32(pb0.x); u.y = f2tf32(pb0.y); u.z = f2tf32(pb0.z); u.w = f2tf32(pb0.w);
            *(uint4*)&Bs[nb][bk0][bn0] = u;
            u.x = f2tf32(pb1.x); u.y = f2tf32(pb1.y); u.z = f2tf32(pb1.z); u.w = f2tf32(pb1.w);
            *(uint4*)&Bs[nb][bk1][bn0] = u;
            __syncthreads();
            buf = nb;
        }
    }

    // epilogue
#pragma unroll
    for (int mi = 0; mi < 2; mi++) {
        const int r0 = brow + wm + mi * 16 + g;
#pragma unroll
        for (int ni = 0; ni < 8; ni++) {
            const int col = bcol + wn + ni * 8 + 2 * t;
            float v0 = acc[mi][ni][0], v1 = acc[mi][ni][1];
            float v2 = acc[mi][ni][2], v3 = acc[mi][ni][3];
            if (act) { v0 = silu_f(v0); v1 = silu_f(v1); v2 = silu_f(v2); v3 = silu_f(v3); }
            float2 lo; lo.x = v0; lo.y = v1;
            float2 hi; hi.x = v2; hi.y = v3;
            *(float2*)(C + (size_t)r0 * Ee + col) = lo;
            *(float2*)(C + (size_t)(r0 + 8) * Ee + col) = hi;
        }
    }
}

// fused qkv: z picks weight/output
__global__ __launch_bounds__(256, 2) void gemm_qkv_tf32(
    const float* __restrict__ A,
    const float* __restrict__ Wq, const float* __restrict__ Wk,
    const float* __restrict__ Wv)
{
    const float* W = (blockIdx.z == 0) ? Wq : (blockIdx.z == 1) ? Wk : Wv;
    float* C = (blockIdx.z == 0) ? g_q : (blockIdx.z == 1) ? g_k : g_v;
    gemm_tf32_core(A, W, C, blockIdx.y * 128, blockIdx.x * 128, 1);
}

__global__ __launch_bounds__(256, 2) void gemm_out_tf32(
    const float* __restrict__ W, float* __restrict__ C)
{
    gemm_tf32_core(g_u, W, C, blockIdx.y * 128, blockIdx.x * 128, 0);
}

// ============================================================
// g1 = x @ Wg1 : [16384,64], K=1024.  128x64 tile, 8x4 microtile (fp32)
// ============================================================
__global__ __launch_bounds__(256) void sgemm_g1(
    const float* __restrict__ A, const float* __restrict__ W)
{
    __shared__ float As[2][8][128];
    __shared__ float Bs[2][8][64];

    const int tid  = threadIdx.x;
    const int tx   = tid & 15;
    const int ty   = tid >> 4;
    const int brow = blockIdx.x * 128;
    const int K = Ee;

    const int arow = tid >> 1;
    const int acol = (tid & 1) * 4;
    const float* Ap = A + (size_t)(brow + arow) * K + acol;

    const int bkr = tid >> 4;
    const int bcl = (tid & 15) * 4;
    const float* Bp = W + (size_t)bkr * Dd + bcl;

    float4 ar = *(const float4*)Ap;
    float4 br = make_float4(0, 0, 0, 0);
    if (tid < 128) br = *(const float4*)Bp;
    As[0][acol + 0][arow] = ar.x;
    As[0][acol + 1][arow] = ar.y;
    As[0][acol + 2][arow] = ar.z;
    As[0][acol + 3][arow] = ar.w;
    if (tid < 128) *(float4*)&Bs[0][bkr][bcl] = br;
    __syncthreads();

    float acc[8][4];
#pragma unroll
    for (int i = 0; i < 8; i++)
#pragma unroll
        for (int j = 0; j < 4; j++) acc[i][j] = 0.0f;

    int buf = 0;
    for (int k0 = 8; k0 <= K; k0 += 8) {
        if (k0 < K) {
            ar = *(const float4*)(Ap + k0);
            if (tid < 128) br = *(const float4*)(Bp + (size_t)k0 * Dd);
        }
#pragma unroll
        for (int kk = 0; kk < 8; kk++) {
            float af[8], bf[4];
            *(float4*)&af[0] = *(float4*)&As[buf][kk][ty * 8];
            *(float4*)&af[4] = *(float4*)&As[buf][kk][ty * 8 + 4];
            *(float4*)&bf[0] = *(float4*)&Bs[buf][kk][tx * 4];
#pragma unroll
            for (int i = 0; i < 8; i++)
#pragma unroll
                for (int j = 0; j < 4; j++)
                    acc[i][j] = fmaf(af[i], bf[j], acc[i][j]);
        }
        if (k0 < K) {
            buf ^= 1;
            As[buf][acol + 0][arow] = ar.x;
            As[buf][acol + 1][arow] = ar.y;
            As[buf][acol + 2][arow] = ar.z;
            As[buf][acol + 3][arow] = ar.w;
            if (tid < 128) *(float4*)&Bs[buf][bkr][bcl] = br;
            __syncthreads();
        }
    }

#pragma unroll
    for (int i = 0; i < 8; i++) {
        float4 o;
        o.x = acc[i][0]; o.y = acc[i][1]; o.z = acc[i][2]; o.w = acc[i][3];
        *(float4*)(g_g1 + (size_t)(brow + ty * 8 + i) * Dd + tx * 4) = o;
    }
}

// ============================================================
// Intra-chunk attention + per-chunk kv contribution A_c (fp32)
// ============================================================
#define SM_QT   0
#define SM_KT   (64*132)
#define SM_VS   (2*64*132)
#define SM_SS   (2*64*132 + 128*68)
#define SM_LAM  (2*64*132 + 128*68 + 128*129)
#define SMEM_INTRA_FLOATS (2*64*132 + 128*68 + 128*129 + 128)

__global__ __launch_bounds__(256) void attn_intra(
    const float* __restrict__ q, const float* __restrict__ k,
    const float* __restrict__ v)
{
    extern __shared__ float sm[];
    float* qT  = sm + SM_QT;
    float* kT  = sm + SM_KT;
    float* vs  = sm + SM_VS;
    float* Ss  = sm + SM_SS;
    float* lamk = sm + SM_LAM;

    const int c = blockIdx.x, h = blockIdx.y, b = blockIdx.z;
    const int tid = threadIdx.x;
    const float s = head_slope(h);
    const size_t base = ((size_t)b * Nn + (size_t)c * Cc) * Ee + (size_t)h * Dd;

#pragma unroll
    for (int t = 0; t < 8; t++) {
        int e = tid + t * 256;
        int row = e >> 4;
        int d4 = (e & 15) * 4;
        const size_t g = base + (size_t)row * Ee + d4;
        float4 qv = *(const float4*)(q + g);
        qT[(d4 + 0) * 132 + row] = qv.x;
        qT[(d4 + 1) * 132 + row] = qv.y;
        qT[(d4 + 2) * 132 + row] = qv.z;
        qT[(d4 + 3) * 132 + row] = qv.w;
        float4 kv4 = *(const float4*)(k + g);
        kT[(d4 + 0) * 132 + row] = kv4.x;
        kT[(d4 + 1) * 132 + row] = kv4.y;
        kT[(d4 + 2) * 132 + row] = kv4.z;
        kT[(d4 + 3) * 132 + row] = kv4.w;
        *(float4*)&vs[row * 68 + d4] = *(const float4*)(v + g);
    }
    if (tid < 128) lamk[tid] = expf(-s * (float)(Cc - 1 - tid));
    __syncthreads();

    const int tx = tid & 15, ty = tid >> 4;

    float acc[8][8];
#pragma unroll
    for (int i = 0; i < 8; i++)
#pragma unroll
        for (int j = 0; j < 8; j++) acc[i][j] = 0.0f;

    for (int d = 0; d < 64; d++) {
        float af[8], bf[8];
        *(float4*)&af[0] = *(float4*)&qT[d * 132 + ty * 8];
        *(float4*)&af[4] = *(float4*)&qT[d * 132 + ty * 8 + 4];
        *(float4*)&bf[0] = *(float4*)&kT[d * 132 + tx * 8];
        *(float4*)&bf[4] = *(float4*)&kT[d * 132 + tx * 8 + 4];
#pragma unroll
        for (int i = 0; i < 8; i++)
#pragma unroll
            for (int j = 0; j < 8; j++)
                acc[i][j] = fmaf(af[i], bf[j], acc[i][j]);
    }
#pragma unroll
    for (int ii = 0; ii < 8; ii++) {
        int i = ty * 8 + ii;
#pragma unroll
        for (int jj = 0; jj < 8; jj++) {
            int j = tx * 8 + jj;
            float val = 0.0f;
            if (i >= j) val = acc[ii][jj] * expf(-s * (float)(i - j));
            Ss[i * 129 + j] = val;
        }
    }
    __syncthreads();

    float oc[8][4];
#pragma unroll
    for (int i = 0; i < 8; i++)
#pragma unroll
        for (int j = 0; j < 4; j++) oc[i][j] = 0.0f;

    for (int j = 0; j < 128; j++) {
        float bv[4];
        *(float4*)bv = *(float4*)&vs[j * 68 + tx * 4];
#pragma unroll
        for (int ii = 0; ii < 8; ii++) {
            float a = Ss[(ty * 8 + ii) * 129 + j];
#pragma unroll
            for (int dd = 0; dd < 4; dd++)
                oc[ii][dd] = fmaf(a, bv[dd], oc[ii][dd]);
        }
    }
#pragma unroll
    for (int ii = 0; ii < 8; ii++) {
        float4 o;
        o.x = oc[ii][0]; o.y = oc[ii][1]; o.z = oc[ii][2]; o.w = oc[ii][3];
        *(float4*)(g_o + base + (size_t)(ty * 8 + ii) * Ee + tx * 4) = o;
    }

    float ac[4][4];
#pragma unroll
    for (int i = 0; i < 4; i++)
#pragma unroll
        for (int j = 0; j < 4; j++) ac[i][j] = 0.0f;

    const int dr = ty * 4;
    for (int j = 0; j < 128; j++) {
        float lam = lamk[j];
        float bv[4];
        *(float4*)bv = *(float4*)&vs[j * 68 + tx * 4];
#pragma unroll
        for (int i = 0; i < 4; i++) {
            float a = kT[(dr + i) * 132 + j] * lam;
#pragma unroll
            for (int e2 = 0; e2 < 4; e2++)
                ac[i][e2] = fmaf(a, bv[e2], ac[i][e2]);
        }
    }
    float* Ab = g_A + ((((size_t)b * Hh + h) * NCk + c) * (Dd * Dd));
#pragma unroll
    for (int i = 0; i < 4; i++) {
        float4 o;
        o.x = ac[i][0]; o.y = ac[i][1]; o.z = ac[i][2]; o.w = ac[i][3];
        *(float4*)&Ab[(dr + i) * Dd + tx * 4] = o;
    }
}

// ============================================================
// kv prefix scan: one (b,h,element) chain per thread.
// 131072 chains of length 64. Coalesced, loads independent.
// ============================================================
__global__ __launch_bounds__(256) void kv_scan()
{
    const int gidx = blockIdx.x * 256 + threadIdx.x;   // 0..131071
    const int bh = gidx >> 12;                          // b*16+h
    const int e  = gidx & 4095;
    const int h  = bh & 15;
    const float s = head_slope(h);
    const float lamc = expf(-s * (float)Cc);

    size_t off = (size_t)bh * NCk * (Dd * Dd) + e;
    float kv = 0.0f;
#pragma unroll 4
    for (int c = 0; c < NCk; c++) {
        g_kv[off] = kv;
        kv = fmaf(lamc, kv, g_A[off]);
        off += Dd * Dd;
    }
}

// ============================================================
// Inter-chunk: o += lam_q[i] * (q @ kv_prefix)   (fp32)
// ============================================================
#define SMEM_INTER_FLOATS (128*68 + 64*68)

__global__ __launch_bounds__(256) void attn_inter(const float* __restrict__ q)
{
    extern __shared__ float sm[];
    float* qs  = sm;
    float* kvs = sm + 128 * 68;

    const int c = blockIdx.x, h = blockIdx.y, b = blockIdx.z;
    const int tid = threadIdx.x;
    const float s = head_slope(h);
    const size_t base = ((size_t)b * Nn + (size_t)c * Cc) * Ee + (size_t)h * Dd;

#pragma unroll
    for (int t = 0; t < 8; t++) {
        int e = tid + t * 256;
        int row = e >> 4;
        int d4 = (e & 15) * 4;
        *(float4*)&qs[row * 68 + d4] = *(const float4*)(q + base + (size_t)row * Ee + d4);
    }
    const float* kvp = g_kv + (((size_t)b * Hh + h) * NCk + c) * (Dd * Dd);
#pragma unroll
    for (int t = 0; t < 4; t++) {
        int e = tid + t * 256;
        int row = e >> 4;
        int d4 = (e & 15) * 4;
        *(float4*)&kvs[row * 68 + d4] = *(const float4*)(kvp + row * Dd + d4);
    }
    __syncthreads();

    const int tx = tid & 15, ty = tid >> 4;
    float oc[8][4];
#pragma unroll
    for (int i = 0; i < 8; i++)
#pragma unroll
        for (int j = 0; j < 4; j++) oc[i][j] = 0.0f;

    for (int e2 = 0; e2 < 64; e2++) {
        float bv[4];
        *(float4*)bv = *(float4*)&kvs[e2 * 68 + tx * 4];
#pragma unroll
        for (int ii = 0; ii < 8; ii++) {
            float a = qs[(ty * 8 + ii) * 68 + e2];
#pragma unroll
            for (int dd = 0; dd < 4; dd++)
                oc[ii][dd] = fmaf(a, bv[dd], oc[ii][dd]);
        }
    }
#pragma unroll
    for (int ii = 0; ii < 8; ii++) {
        int i = ty * 8 + ii;
        float lamq = expf(-s * (float)(i + 1));
        float* op = g_o + base + (size_t)i * Ee + tx * 4;
        float4 prev = *(float4*)op;
        prev.x = fmaf(lamq, oc[ii][0], prev.x);
        prev.y = fmaf(lamq, oc[ii][1], prev.y);
        prev.z = fmaf(lamq, oc[ii][2], prev.z);
        prev.w = fmaf(lamq, oc[ii][3], prev.w);
        *(float4*)op = prev;
    }
}

// ============================================================
// LayerNorm + gate (g1 @ Wg2 -> sigmoid) + multiply -> g_u
// ============================================================
__global__ __launch_bounds__(256) void ln_gate(
    const float* __restrict__ gamma, const float* __restrict__ beta,
    const float* __restrict__ Wg2)
{
    __shared__ float os[8 * 1024];
    __shared__ float g1s[8 * 64];
    __shared__ float wsum[8], wsq[8];
    __shared__ float mu_s[8], rs_s[8];

    const int tid = threadIdx.x;
    const size_t row0 = (size_t)blockIdx.x * 8;

#pragma unroll
    for (int t = 0; t < 8; t++) {
        int e = tid + t * 256;
        int r = e >> 8;
        int c4 = (e & 255) * 4;
        *(float4*)&os[r * 1024 + c4] = *(const float4*)(g_o + (row0 + r) * 1024 + c4);
    }
    if (tid < 128) {
        int r = tid >> 4;
        int c4 = (tid & 15) * 4;
        *(float4*)&g1s[r * 64 + c4] = *(const float4*)(g_g1 + (row0 + r) * 64 + c4);
    }
    __syncthreads();

    const int lane = tid & 31, wid = tid >> 5;

    for (int r = 0; r < 8; r++) {
        float sum = 0.0f;
#pragma unroll
        for (int t = 0; t < 4; t++) sum += os[r * 1024 + tid + t * 256];
#pragma unroll
        for (int o = 16; o; o >>= 1) sum += __shfl_xor_sync(0xffffffffu, sum, o);
        if (lane == 0) wsum[wid] = sum;
        __syncthreads();
        if (tid == 0) {
            float S = 0.0f;
            for (int w = 0; w < 8; w++) S += wsum[w];
            mu_s[r] = S * (1.0f / 1024.0f);
        }
        __syncthreads();
    }
    for (int r = 0; r < 8; r++) {
        float mu = mu_s[r];
        float sq = 0.0f;
#pragma unroll
        for (int t = 0; t < 4; t++) {
            float d = os[r * 1024 + tid + t * 256] - mu;
            sq = fmaf(d, d, sq);
        }
#pragma unroll
        for (int o = 16; o; o >>= 1) sq += __shfl_xor_sync(0xffffffffu, sq, o);
        if (lane == 0) wsq[wid] = sq;
        __syncthreads();
        if (tid == 0) {
            float Q = 0.0f;
            for (int w = 0; w < 8; w++) Q += wsq[w];
            rs_s[r] = rsqrtf(Q * (1.0f / 1024.0f) + 1e-5f);
        }
        __syncthreads();
    }

    const int r = wid;
    const int cbase = lane * 4;
    const float mu = mu_s[r];
    const float rs = rs_s[r];
#pragma unroll
    for (int t = 0; t < 8; t++) {
        int col = cbase + t * 128;
        float4 ov = *(float4*)&os[r * 1024 + col];
        float4 gd = make_float4(0, 0, 0, 0);
        for (int kk = 0; kk < 64; kk++) {
            float gk = g1s[r * 64 + kk];
            float4 w = *(const float4*)(Wg2 + (size_t)kk * 1024 + col);
            gd.x = fmaf(gk, w.x, gd.x);
            gd.y = fmaf(gk, w.y, gd.y);
            gd.z = fmaf(gk, w.z, gd.z);
            gd.w = fmaf(gk, w.w, gd.w);
        }
        float4 gm = *(const float4*)(gamma + col);
        float4 bt = *(const float4*)(beta + col);
        float4 u;
        u.x = (fmaf((ov.x - mu) * rs, gm.x, bt.x)) * (1.0f / (1.0f + expf(-gd.x)));
        u.y = (fmaf((ov.y - mu) * rs, gm.y, bt.y)) * (1.0f / (1.0f + expf(-gd.y)));
        u.z = (fmaf((ov.z - mu) * rs, gm.z, bt.z)) * (1.0f / (1.0f + expf(-gd.z)));
        u.w = (fmaf((ov.w - mu) * rs, gm.w, bt.w)) * (1.0f / (1.0f + expf(-gd.w)));
        *(float4*)(g_u + (row0 + r) * 1024 + col) = u;
    }
}

// ============================================================
// host launch
// ============================================================
extern "C" void kernel_launch(void* const* d_in, const int* in_sizes, int n_in,
                              void* d_out, int out_size)
{
    const float* x     = (const float*)d_in[0];
    const float* Wq    = (const float*)d_in[1];
    const float* Wk    = (const float*)d_in[2];
    const float* Wv    = (const float*)d_in[3];
    const float* Wo    = (const float*)d_in[4];
    const float* gamma = (const float*)d_in[5];
    const float* beta  = (const float*)d_in[6];
    const float* Wg1   = (const float*)d_in[7];
    const float* Wg2   = (const float*)d_in[8];
    float* out = (float*)d_out;

    static bool init_done = false;
    static float *qp, *kp, *vp;
    if (!init_done) {
        cudaGetSymbolAddress((void**)&qp, g_q);
        cudaGetSymbolAddress((void**)&kp, g_k);
        cudaGetSymbolAddress((void**)&vp, g_v);
        cudaFuncSetAttribute(attn_intra, cudaFuncAttributeMaxDynamicSharedMemorySize,
                             SMEM_INTRA_FLOATS * (int)sizeof(float));
        cudaFuncSetAttribute(attn_inter, cudaFuncAttributeMaxDynamicSharedMemorySize,
                             SMEM_INTER_FLOATS * (int)sizeof(float));
        init_done = true;
    }

    const int smem_intra = SMEM_INTRA_FLOATS * (int)sizeof(float);
    const int smem_inter = SMEM_INTER_FLOATS * (int)sizeof(float);

    dim3 blk(256);

    gemm_qkv_tf32<<<dim3(Ee / 128, Mm / 128, 3), blk>>>(x, Wq, Wk, Wv);
    sgemm_g1<<<Mm / 128, blk>>>(x, Wg1);

    attn_intra<<<dim3(NCk, Hh, Bb), blk, smem_intra>>>(qp, kp, vp);
    kv_scan<<<512, blk>>>();
    attn_inter<<<dim3(NCk, Hh, Bb), blk, smem_inter>>>(qp);

    ln_gate<<<Mm / 8, blk>>>(gamma, beta, Wg2);

    gemm_out_tf32<<<dim3(Ee / 128, Mm / 128), blk>>>(Wo, out);
}

// round 6
// speedup vs baseline: 2.3153x; 1.0281x over previous
#include <cuda_runtime.h>
#include <math.h>
#include <stdint.h>

// ---------------- problem constants ----------------
#define Bb   2
#define Nn   8192
#define Ee   1024
#define Hh   16
#define Dd   64
#define Cc   128
#define NCk  64
#define Mm   (Bb*Nn)

// ---------------- device scratch ----------------
__device__ float g_q[(size_t)Mm*Ee];
__device__ float g_k[(size_t)Mm*Ee];
__device__ float g_v[(size_t)Mm*Ee];
__device__ float g_o[(size_t)Mm*Ee];
__device__ float g_A [(size_t)Bb*Hh*NCk*Dd*Dd];
__device__ float g_kv[(size_t)Bb*Hh*NCk*Dd*Dd];
__device__ float g_g1[(size_t)Mm*Dd];
__device__ uint32_t g_xc[(size_t)Mm*Ee];       // x pre-converted to tf32 bits
__device__ uint32_t g_uc[(size_t)Mm*Ee];       // gated-LN output, tf32 bits
__device__ uint32_t g_Wc[4][(size_t)Ee*Ee];    // Wq,Wk,Wv,Wo tf32 bits (layout unchanged [k][n])

__device__ __forceinline__ float head_slope(int h) {
    return exp2f(-0.5f * (float)(h + 1)) * 1.00001f;
}
__device__ __forceinline__ float silu_f(float v) { return v / (1.0f + expf(-v)); }

__device__ __forceinline__ uint32_t f2tf32(float x) {
    uint32_t r;
    asm("cvt.rna.tf32.f32 %0, %1;" : "=r"(r) : "f"(x));
    return r;
}
__device__ __forceinline__ uint32_t s2u(const void* p) {
    return (uint32_t)__cvta_generic_to_shared(p);
}

#define CP16(dst, src) \
    asm volatile("cp.async.cg.shared.global [%0], [%1], 16;" :: "r"(dst), "l"(src) : "memory")
#define CP_COMMIT() asm volatile("cp.async.commit_group;" ::: "memory")
#define CP_WAIT2()  asm volatile("cp.async.wait_group 2;" ::: "memory")

__device__ __forceinline__ void mma_tf32(
    float c[4], const uint32_t a[4], const uint32_t b[2])
{
    asm volatile(
        "mma.sync.aligned.m16n8k8.row.col.f32.tf32.tf32.f32 "
        "{%0,%1,%2,%3}, {%4,%5,%6,%7}, {%8,%9}, {%0,%1,%2,%3};"
        : "+f"(c[0]), "+f"(c[1]), "+f"(c[2]), "+f"(c[3])
        : "r"(a[0]), "r"(a[1]), "r"(a[2]), "r"(a[3]),
          "r"(b[0]), "r"(b[1]));
}

// ============================================================
// Operand conversion kernels (one-time per launch)
// ============================================================
__global__ __launch_bounds__(256) void conv_x(const float* __restrict__ x)
{
    size_t i = (size_t)(blockIdx.x * 256 + threadIdx.x);
    const size_t nf4 = (size_t)Mm * Ee / 4;
    const size_t stride = (size_t)gridDim.x * 256;
    for (; i < nf4; i += stride) {
        float4 v = ((const float4*)x)[i];
        uint4 u;
        u.x = f2tf32(v.x); u.y = f2tf32(v.y); u.z = f2tf32(v.z); u.w = f2tf32(v.w);
        ((uint4*)g_xc)[i] = u;
    }
}

__global__ __launch_bounds__(256) void conv_w(
    const float* __restrict__ Wq, const float* __restrict__ Wk,
    const float* __restrict__ Wv, const float* __restrict__ Wo)
{
    const float* W = (blockIdx.y == 0) ? Wq : (blockIdx.y == 1) ? Wk :
                     (blockIdx.y == 2) ? Wv : Wo;
    uint32_t* Wc = g_Wc[blockIdx.y];
    size_t i = (size_t)(blockIdx.x * 256 + threadIdx.x);
    const size_t nf4 = (size_t)Ee * Ee / 4;
    const size_t stride = (size_t)gridDim.x * 256;
    for (; i < nf4; i += stride) {
        float4 v = ((const float4*)W)[i];
        uint4 u;
        u.x = f2tf32(v.x); u.y = f2tf32(v.y); u.z = f2tf32(v.z); u.w = f2tf32(v.w);
        ((uint4*)Wc)[i] = u;
    }
}

// ============================================================
// tf32 mma.sync GEMM, 4-stage cp.async pipeline.
// C[128,128] tile; 8 warps (4m x 2n), warp tile 32x64, m16n8k8.
// As[stage][128][20] (pad 20: A-frag LDS conflict-free),
// Bs[stage][16][136] (pad 136: B-frag LDS conflict-free).
// ============================================================
#define PA 20
#define PB 136
#define STG 4
#define GEMM_SMEM ((STG*128*PA + STG*16*PB) * 4)

__device__ void gemm_core(
    const uint32_t* __restrict__ A, const uint32_t* __restrict__ B,
    float* __restrict__ C, int brow, int bcol, int act)
{
    extern __shared__ uint32_t smem[];
    uint32_t* AsBase = smem;                     // [STG][128][PA]
    uint32_t* BsBase = smem + STG * 128 * PA;    // [STG][16][PB]

    const int tid  = threadIdx.x;
    const int wid  = tid >> 5;
    const int lane = tid & 31;
    const int g = lane >> 2, t = lane & 3;
    const int wm = (wid & 3) * 32;
    const int wn = (wid >> 2) * 64;

    // G2S plan: A rows a0, a0+64 (16B of k each); B rows bk, bk+8 (16B of n each)
    const int a0 = tid >> 2;              // 0..63
    const int kc = (tid & 3) * 4;         // k offset
    const int bk = tid >> 5;              // 0..7
    const int bn = (tid & 31) * 4;

    const uint32_t* Ag0 = A + (size_t)(brow + a0) * Ee + kc;
    const uint32_t* Ag1 = A + (size_t)(brow + a0 + 64) * Ee + kc;
    const uint32_t* Bg0 = B + (size_t)bk * Ee + bcol + bn;
    const uint32_t* Bg1 = B + (size_t)(bk + 8) * Ee + bcol + bn;

    const uint32_t dA0 = s2u(&AsBase[(size_t)a0 * PA + kc]);
    const uint32_t dA1 = s2u(&AsBase[(size_t)(a0 + 64) * PA + kc]);
    const uint32_t dB0 = s2u(&BsBase[(size_t)bk * PB + bn]);
    const uint32_t dB1 = s2u(&BsBase[(size_t)(bk + 8) * PB + bn]);
    const uint32_t strideA = 128 * PA * 4;   // bytes per A stage
    const uint32_t strideB = 16 * PB * 4;    // bytes per B stage

    float acc[2][8][4];
#pragma unroll
    for (int mi = 0; mi < 2; mi++)
#pragma unroll
        for (int ni = 0; ni < 8; ni++)
#pragma unroll
            for (int j = 0; j < 4; j++) acc[mi][ni][j] = 0.0f;

    // prologue: stages 0..2
#pragma unroll
    for (int p = 0; p < 3; p++) {
        CP16(dA0 + p * strideA, Ag0 + p * 16);
        CP16(dA1 + p * strideA, Ag1 + p * 16);
        CP16(dB0 + p * strideB, Bg0 + (size_t)(p * 16) * Ee);
        CP16(dB1 + p * strideB, Bg1 + (size_t)(p * 16) * Ee);
        CP_COMMIT();
    }

    for (int c = 0; c < 64; c++) {
        CP_WAIT2();
        __syncthreads();

        if (c + 3 < 64) {
            const int s = (c + 3) & 3;
            CP16(dA0 + s * strideA, Ag0 + (c + 3) * 16);
            CP16(dA1 + s * strideA, Ag1 + (c + 3) * 16);
            CP16(dB0 + s * strideB, Bg0 + (size_t)((c + 3) * 16) * Ee);
            CP16(dB1 + s * strideB, Bg1 + (size_t)((c + 3) * 16) * Ee);
            CP_COMMIT();
        }

        const int s = c & 3;
        const uint32_t* As = AsBase + (size_t)s * 128 * PA;
        const uint32_t* Bs = BsBase + (size_t)s * 16 * PB;

#pragma unroll
        for (int kk = 0; kk < 16; kk += 8) {
            uint32_t afr[2][4], bfr[8][2];
#pragma unroll
            for (int mi = 0; mi < 2; mi++) {
                const int m = wm + mi * 16 + g;
                afr[mi][0] = As[(size_t)m * PA + kk + t];
                afr[mi][1] = As[(size_t)(m + 8) * PA + kk + t];
                afr[mi][2] = As[(size_t)m * PA + kk + t + 4];
                afr[mi][3] = As[(size_t)(m + 8) * PA + kk + t + 4];
            }
#pragma unroll
            for (int ni = 0; ni < 8; ni++) {
                const int n = wn + ni * 8 + g;
                bfr[ni][0] = Bs[(size_t)(kk + t) * PB + n];
                bfr[ni][1] = Bs[(size_t)(kk + t + 4) * PB + n];
            }
#pragma unroll
            for (int mi = 0; mi < 2; mi++)
#pragma unroll
                for (int ni = 0; ni < 8; ni++)
                    mma_tf32(acc[mi][ni], afr[mi], bfr[ni]);
        }
    }

    // epilogue
#pragma unroll
    for (int mi = 0; mi < 2; mi++) {
        const int r0 = brow + wm + mi * 16 + g;
#pragma unroll
        for (int ni = 0; ni < 8; ni++) {
            const int col = bcol + wn + ni * 8 + 2 * t;
            float v0 = acc[mi][ni][0], v1 = acc[mi][ni][1];
            float v2 = acc[mi][ni][2], v3 = acc[mi][ni][3];
            if (act) { v0 = silu_f(v0); v1 = silu_f(v1); v2 = silu_f(v2); v3 = silu_f(v3); }
            float2 lo; lo.x = v0; lo.y = v1;
            float2 hi; hi.x = v2; hi.y = v3;
            *(float2*)(C + (size_t)r0 * Ee + col) = lo;
            *(float2*)(C + (size_t)(r0 + 8) * Ee + col) = hi;
        }
    }
}

__global__ __launch_bounds__(256) void gemm_qkv_tf32()
{
    const uint32_t* B = g_Wc[blockIdx.z];
    float* C = (blockIdx.z == 0) ? g_q : (blockIdx.z == 1) ? g_k : g_v;
    gemm_core(g_xc, B, C, blockIdx.y * 128, blockIdx.x * 128, 1);
}

__global__ __launch_bounds__(256) void gemm_out_tf32(float* __restrict__ C)
{
    gemm_core(g_uc, g_Wc[3], C, blockIdx.y * 128, blockIdx.x * 128, 0);
}

// ============================================================
// g1 = x @ Wg1 : [16384,64], K=1024 (fp32 FFMA)
// ============================================================
__global__ __launch_bounds__(256) void sgemm_g1(
    const float* __restrict__ A, const float* __restrict__ W)
{
    __shared__ float As[2][8][128];
    __shared__ float Bs[2][8][64];

    const int tid  = threadIdx.x;
    const int tx   = tid & 15;
    const int ty   = tid >> 4;
    const int brow = blockIdx.x * 128;
    const int K = Ee;

    const int arow = tid >> 1;
    const int acol = (tid & 1) * 4;
    const float* Ap = A + (size_t)(brow + arow) * K + acol;

    const int bkr = tid >> 4;
    const int bcl = (tid & 15) * 4;
    const float* Bp = W + (size_t)bkr * Dd + bcl;

    float4 ar = *(const float4*)Ap;
    float4 br = make_float4(0, 0, 0, 0);
    if (tid < 128) br = *(const float4*)Bp;
    As[0][acol + 0][arow] = ar.x;
    As[0][acol + 1][arow] = ar.y;
    As[0][acol + 2][arow] = ar.z;
    As[0][acol + 3][arow] = ar.w;
    if (tid < 128) *(float4*)&Bs[0][bkr][bcl] = br;
    __syncthreads();

    float acc[8][4];
#pragma unroll
    for (int i = 0; i < 8; i++)
#pragma unroll
        for (int j = 0; j < 4; j++) acc[i][j] = 0.0f;

    int buf = 0;
    for (int k0 = 8; k0 <= K; k0 += 8) {
        if (k0 < K) {
            ar = *(const float4*)(Ap + k0);
            if (tid < 128) br = *(const float4*)(Bp + (size_t)k0 * Dd);
        }
#pragma unroll
        for (int kk = 0; kk < 8; kk++) {
            float af[8], bf[4];
            *(float4*)&af[0] = *(float4*)&As[buf][kk][ty * 8];
            *(float4*)&af[4] = *(float4*)&As[buf][kk][ty * 8 + 4];
            *(float4*)&bf[0] = *(float4*)&Bs[buf][kk][tx * 4];
#pragma unroll
            for (int i = 0; i < 8; i++)
#pragma unroll
                for (int j = 0; j < 4; j++)
                    acc[i][j] = fmaf(af[i], bf[j], acc[i][j]);
        }
        if (k0 < K) {
            buf ^= 1;
            As[buf][acol + 0][arow] = ar.x;
            As[buf][acol + 1][arow] = ar.y;
            As[buf][acol + 2][arow] = ar.z;
            As[buf][acol + 3][arow] = ar.w;
            if (tid < 128) *(float4*)&Bs[buf][bkr][bcl] = br;
            __syncthreads();
        }
    }

#pragma unroll
    for (int i = 0; i < 8; i++) {
        float4 o;
        o.x = acc[i][0]; o.y = acc[i][1]; o.z = acc[i][2]; o.w = acc[i][3];
        *(float4*)(g_g1 + (size_t)(brow + ty * 8 + i) * Dd + tx * 4) = o;
    }
}

// ============================================================
// Intra-chunk attention + per-chunk kv contribution A_c (fp32)
// ============================================================
#define SM_QT   0
#define SM_KT   (64*132)
#define SM_VS   (2*64*132)
#define SM_SS   (2*64*132 + 128*68)
#define SM_LAM  (2*64*132 + 128*68 + 128*129)
#define SMEM_INTRA_FLOATS (2*64*132 + 128*68 + 128*129 + 128)

__global__ __launch_bounds__(256) void attn_intra(
    const float* __restrict__ q, const float* __restrict__ k,
    const float* __restrict__ v)
{
    extern __shared__ float sm[];
    float* qT  = sm + SM_QT;
    float* kT  = sm + SM_KT;
    float* vs  = sm + SM_VS;
    float* Ss  = sm + SM_SS;
    float* lamk = sm + SM_LAM;

    const int c = blockIdx.x, h = blockIdx.y, b = blockIdx.z;
    const int tid = threadIdx.x;
    const float s = head_slope(h);
    const size_t base = ((size_t)b * Nn + (size_t)c * Cc) * Ee + (size_t)h * Dd;

#pragma unroll
    for (int t = 0; t < 8; t++) {
        int e = tid + t * 256;
        int row = e >> 4;
        int d4 = (e & 15) * 4;
        const size_t g = base + (size_t)row * Ee + d4;
        float4 qv = *(const float4*)(q + g);
        qT[(d4 + 0) * 132 + row] = qv.x;
        qT[(d4 + 1) * 132 + row] = qv.y;
        qT[(d4 + 2) * 132 + row] = qv.z;
        qT[(d4 + 3) * 132 + row] = qv.w;
        float4 kv4 = *(const float4*)(k + g);
        kT[(d4 + 0) * 132 + row] = kv4.x;
        kT[(d4 + 1) * 132 + row] = kv4.y;
        kT[(d4 + 2) * 132 + row] = kv4.z;
        kT[(d4 + 3) * 132 + row] = kv4.w;
        *(float4*)&vs[row * 68 + d4] = *(const float4*)(v + g);
    }
    if (tid < 128) lamk[tid] = expf(-s * (float)(Cc - 1 - tid));
    __syncthreads();

    const int tx = tid & 15, ty = tid >> 4;

    float acc[8][8];
#pragma unroll
    for (int i = 0; i < 8; i++)
#pragma unroll
        for (int j = 0; j < 8; j++) acc[i][j] = 0.0f;

    for (int d = 0; d < 64; d++) {
        float af[8], bf[8];
        *(float4*)&af[0] = *(float4*)&qT[d * 132 + ty * 8];
        *(float4*)&af[4] = *(float4*)&qT[d * 132 + ty * 8 + 4];
        *(float4*)&bf[0] = *(float4*)&kT[d * 132 + tx * 8];
        *(float4*)&bf[4] = *(float4*)&kT[d * 132 + tx * 8 + 4];
#pragma unroll
        for (int i = 0; i < 8; i++)
#pragma unroll
            for (int j = 0; j < 8; j++)
                acc[i][j] = fmaf(af[i], bf[j], acc[i][j]);
    }
#pragma unroll
    for (int ii = 0; ii < 8; ii++) {
        int i = ty * 8 + ii;
#pragma unroll
        for (int jj = 0; jj < 8; jj++) {
            int j = tx * 8 + jj;
            float val = 0.0f;
            if (i >= j) val = acc[ii][jj] * expf(-s * (float)(i - j));
            Ss[i * 129 + j] = val;
        }
    }
    __syncthreads();

    float oc[8][4];
#pragma unroll
    for (int i = 0; i < 8; i++)
#pragma unroll
        for (int j = 0; j < 4; j++) oc[i][j] = 0.0f;

    for (int j = 0; j < 128; j++) {
        float bv[4];
        *(float4*)bv = *(float4*)&vs[j * 68 + tx * 4];
#pragma unroll
        for (int ii = 0; ii < 8; ii++) {
            float a = Ss[(ty * 8 + ii) * 129 + j];
#pragma unroll
            for (int dd = 0; dd < 4; dd++)
                oc[ii][dd] = fmaf(a, bv[dd], oc[ii][dd]);
        }
    }
#pragma unroll
    for (int ii = 0; ii < 8; ii++) {
        float4 o;
        o.x = oc[ii][0]; o.y = oc[ii][1]; o.z = oc[ii][2]; o.w = oc[ii][3];
        *(float4*)(g_o + base + (size_t)(ty * 8 + ii) * Ee + tx * 4) = o;
    }

    float ac[4][4];
#pragma unroll
    for (int i = 0; i < 4; i++)
#pragma unroll
        for (int j = 0; j < 4; j++) ac[i][j] = 0.0f;

    const int dr = ty * 4;
    for (int j = 0; j < 128; j++) {
        float lam = lamk[j];
        float bv[4];
        *(float4*)bv = *(float4*)&vs[j * 68 + tx * 4];
#pragma unroll
        for (int i = 0; i < 4; i++) {
            float a = kT[(dr + i) * 132 + j] * lam;
#pragma unroll
            for (int e2 = 0; e2 < 4; e2++)
                ac[i][e2] = fmaf(a, bv[e2], ac[i][e2]);
        }
    }
    float* Ab = g_A + ((((size_t)b * Hh + h) * NCk + c) * (Dd * Dd));
#pragma unroll
    for (int i = 0; i < 4; i++) {
        float4 o;
        o.x = ac[i][0]; o.y = ac[i][1]; o.z = ac[i][2]; o.w = ac[i][3];
        *(float4*)&Ab[(dr + i) * Dd + tx * 4] = o;
    }
}

// ============================================================
// kv prefix scan: one (b,h,element) chain per thread
// ============================================================
__global__ __launch_bounds__(256) void kv_scan()
{
    const int gidx = blockIdx.x * 256 + threadIdx.x;
    const int bh = gidx >> 12;
    const int e  = gidx & 4095;
    const int h  = bh & 15;
    const float s = head_slope(h);
    const float lamc = expf(-s * (float)Cc);

    size_t off = (size_t)bh * NCk * (Dd * Dd) + e;
    float kv = 0.0f;
#pragma unroll 4
    for (int c = 0; c < NCk; c++) {
        g_kv[off] = kv;
        kv = fmaf(lamc, kv, g_A[off]);
        off += Dd * Dd;
    }
}

// ============================================================
// Inter-chunk: o += lam_q[i] * (q @ kv_prefix)
// ============================================================
#define SMEM_INTER_FLOATS (128*68 + 64*68)

__global__ __launch_bounds__(256) void attn_inter(const float* __restrict__ q)
{
    extern __shared__ float sm[];
    float* qs  = sm;
    float* kvs = sm + 128 * 68;

    const int c = blockIdx.x, h = blockIdx.y, b = blockIdx.z;
    const int tid = threadIdx.x;
    const float s = head_slope(h);
    const size_t base = ((size_t)b * Nn + (size_t)c * Cc) * Ee + (size_t)h * Dd;

#pragma unroll
    for (int t = 0; t < 8; t++) {
        int e = tid + t * 256;
        int row = e >> 4;
        int d4 = (e & 15) * 4;
        *(float4*)&qs[row * 68 + d4] = *(const float4*)(q + base + (size_t)row * Ee + d4);
    }
    const float* kvp = g_kv + (((size_t)b * Hh + h) * NCk + c) * (Dd * Dd);
#pragma unroll
    for (int t = 0; t < 4; t++) {
        int e = tid + t * 256;
        int row = e >> 4;
        int d4 = (e & 15) * 4;
        *(float4*)&kvs[row * 68 + d4] = *(const float4*)(kvp + row * Dd + d4);
    }
    __syncthreads();

    const int tx = tid & 15, ty = tid >> 4;
    float oc[8][4];
#pragma unroll
    for (int i = 0; i < 8; i++)
#pragma unroll
        for (int j = 0; j < 4; j++) oc[i][j] = 0.0f;

    for (int e2 = 0; e2 < 64; e2++) {
        float bv[4];
        *(float4*)bv = *(float4*)&kvs[e2 * 68 + tx * 4];
#pragma unroll
        for (int ii = 0; ii < 8; ii++) {
            float a = qs[(ty * 8 + ii) * 68 + e2];
#pragma unroll
            for (int dd = 0; dd < 4; dd++)
                oc[ii][dd] = fmaf(a, bv[dd], oc[ii][dd]);
        }
    }
#pragma unroll
    for (int ii = 0; ii < 8; ii++) {
        int i = ty * 8 + ii;
        float lamq = expf(-s * (float)(i + 1));
        float* op = g_o + base + (size_t)i * Ee + tx * 4;
        float4 prev = *(float4*)op;
        prev.x = fmaf(lamq, oc[ii][0], prev.x);
        prev.y = fmaf(lamq, oc[ii][1], prev.y);
        prev.z = fmaf(lamq, oc[ii][2], prev.z);
        prev.w = fmaf(lamq, oc[ii][3], prev.w);
        *(float4*)op = prev;
    }
}

// ============================================================
// LayerNorm + gate (g1 @ Wg2 -> sigmoid) + multiply -> g_uc (tf32 bits)
// ============================================================
__global__ __launch_bounds__(256) void ln_gate(
    const float* __restrict__ gamma, const float* __restrict__ beta,
    const float* __restrict__ Wg2)
{
    __shared__ float os[8 * 1024];
    __shared__ float g1s[8 * 64];
    __shared__ float wsum[8], wsq[8];
    __shared__ float mu_s[8], rs_s[8];

    const int tid = threadIdx.x;
    const size_t row0 = (size_t)blockIdx.x * 8;

#pragma unroll
    for (int t = 0; t < 8; t++) {
        int e = tid + t * 256;
        int r = e >> 8;
        int c4 = (e & 255) * 4;
        *(float4*)&os[r * 1024 + c4] = *(const float4*)(g_o + (row0 + r) * 1024 + c4);
    }
    if (tid < 128) {
        int r = tid >> 4;
        int c4 = (tid & 15) * 4;
        *(float4*)&g1s[r * 64 + c4] = *(const float4*)(g_g1 + (row0 + r) * 64 + c4);
    }
    __syncthreads();

    const int lane = tid & 31, wid = tid >> 5;

    for (int r = 0; r < 8; r++) {
        float sum = 0.0f;
#pragma unroll
        for (int t = 0; t < 4; t++) sum += os[r * 1024 + tid + t * 256];
#pragma unroll
        for (int o = 16; o; o >>= 1) sum += __shfl_xor_sync(0xffffffffu, sum, o);
        if (lane == 0) wsum[wid] = sum;
        __syncthreads();
        if (tid == 0) {
            float S = 0.0f;
            for (int w = 0; w < 8; w++) S += wsum[w];
            mu_s[r] = S * (1.0f / 1024.0f);
        }
        __syncthreads();
    }
    for (int r = 0; r < 8; r++) {
        float mu = mu_s[r];
        float sq = 0.0f;
#pragma unroll
        for (int t = 0; t < 4; t++) {
            float d = os[r * 1024 + tid + t * 256] - mu;
            sq = fmaf(d, d, sq);
        }
#pragma unroll
        for (int o = 16; o; o >>= 1) sq += __shfl_xor_sync(0xffffffffu, sq, o);
        if (lane == 0) wsq[wid] = sq;
        __syncthreads();
        if (tid == 0) {
            float Q = 0.0f;
            for (int w = 0; w < 8; w++) Q += wsq[w];
            rs_s[r] = rsqrtf(Q * (1.0f / 1024.0f) + 1e-5f);
        }
        __syncthreads();
    }

    const int r = wid;
    const int cbase = lane * 4;
    const float mu = mu_s[r];
    const float rs = rs_s[r];
#pragma unroll
    for (int t = 0; t < 8; t++) {
        int col = cbase + t * 128;
        float4 ov = *(float4*)&os[r * 1024 + col];
        float4 gd = make_float4(0, 0, 0, 0);
        for (int kk = 0; kk < 64; kk++) {
            float gk = g1s[r * 64 + kk];
            float4 w = *(const float4*)(Wg2 + (size_t)kk * 1024 + col);
            gd.x = fmaf(gk, w.x, gd.x);
            gd.y = fmaf(gk, w.y, gd.y);
            gd.z = fmaf(gk, w.z, gd.z);
            gd.w = fmaf(gk, w.w, gd.w);
        }
        float4 gm = *(const float4*)(gamma + col);
        float4 bt = *(const float4*)(beta + col);
        uint4 u;
        u.x = f2tf32((fmaf((ov.x - mu) * rs, gm.x, bt.x)) * (1.0f / (1.0f + expf(-gd.x))));
        u.y = f2tf32((fmaf((ov.y - mu) * rs, gm.y, bt.y)) * (1.0f / (1.0f + expf(-gd.y))));
        u.z = f2tf32((fmaf((ov.z - mu) * rs, gm.z, bt.z)) * (1.0f / (1.0f + expf(-gd.z))));
        u.w = f2tf32((fmaf((ov.w - mu) * rs, gm.w, bt.w)) * (1.0f / (1.0f + expf(-gd.w))));
        *(uint4*)(g_uc + (row0 + r) * 1024 + col) = u;
    }
}

// ============================================================
// host launch
// ============================================================
extern "C" void kernel_launch(void* const* d_in, const int* in_sizes, int n_in,
                              void* d_out, int out_size)
{
    const float* x     = (const float*)d_in[0];
    const float* Wq    = (const float*)d_in[1];
    const float* Wk    = (const float*)d_in[2];
    const float* Wv    = (const float*)d_in[3];
    const float* Wo    = (const float*)d_in[4];
    const float* gamma = (const float*)d_in[5];
    const float* beta  = (const float*)d_in[6];
    const float* Wg1   = (const float*)d_in[7];
    const float* Wg2   = (const float*)d_in[8];
    float* out = (float*)d_out;

    static bool init_done = false;
    static float *qp, *kp, *vp;
    if (!init_done) {
        cudaGetSymbolAddress((void**)&qp, g_q);
        cudaGetSymbolAddress((void**)&kp, g_k);
        cudaGetSymbolAddress((void**)&vp, g_v);
        cudaFuncSetAttribute(attn_intra, cudaFuncAttributeMaxDynamicSharedMemorySize,
                             SMEM_INTRA_FLOATS * (int)sizeof(float));
        cudaFuncSetAttribute(attn_inter, cudaFuncAttributeMaxDynamicSharedMemorySize,
                             SMEM_INTER_FLOATS * (int)sizeof(float));
        cudaFuncSetAttribute(gemm_qkv_tf32, cudaFuncAttributeMaxDynamicSharedMemorySize,
                             GEMM_SMEM);
        cudaFuncSetAttribute(gemm_out_tf32, cudaFuncAttributeMaxDynamicSharedMemorySize,
                             GEMM_SMEM);
        init_done = true;
    }

    const int smem_intra = SMEM_INTRA_FLOATS * (int)sizeof(float);
    const int smem_inter = SMEM_INTER_FLOATS * (int)sizeof(float);

    dim3 blk(256);

    conv_x<<<4096, blk>>>(x);
    conv_w<<<dim3(1024, 4), blk>>>(Wq, Wk, Wv, Wo);

    gemm_qkv_tf32<<<dim3(Ee / 128, Mm / 128, 3), blk, GEMM_SMEM>>>();
    sgemm_g1<<<Mm / 128, blk>>>(x, Wg1);

    attn_intra<<<dim3(NCk, Hh, Bb), blk, smem_intra>>>(qp, kp, vp);
    kv_scan<<<512, blk>>>();
    attn_inter<<<dim3(NCk, Hh, Bb), blk, smem_inter>>>(qp);

    ln_gate<<<Mm / 8, blk>>>(gamma, beta, Wg2);

    gemm_out_tf32<<<dim3(Ee / 128, Mm / 128), blk, GEMM_SMEM>>>(out);
}

// round 7
// speedup vs baseline: 3.1843x; 1.3753x over previous
#include <cuda_runtime.h>
#include <cuda_fp16.h>
#include <math.h>
#include <stdint.h>

// ---------------- problem constants ----------------
#define Bb   2
#define Nn   8192
#define Ee   1024
#define Hh   16
#define Dd   64
#define Cc   128
#define NCk  64
#define Mm   (Bb*Nn)

// ---------------- device scratch ----------------
__device__ float g_q[(size_t)Mm*Ee];
__device__ float g_k[(size_t)Mm*Ee];
__device__ float g_v[(size_t)Mm*Ee];
__device__ float g_o[(size_t)Mm*Ee];
__device__ float g_A [(size_t)Bb*Hh*NCk*Dd*Dd];
__device__ float g_kv[(size_t)Bb*Hh*NCk*Dd*Dd];
__device__ float g_g1[(size_t)Mm*Dd];
__device__ uint32_t g_xh[(size_t)Mm*Ee/2];        // x as half2, [m][k]
__device__ uint32_t g_uh[(size_t)Mm*Ee/2];        // gated-LN out as half2, [m][k]
__device__ uint32_t g_Wh[4][(size_t)Ee*Ee/2];     // W^T as half2: [n][k]
__device__ uint32_t g_Wg1h[(size_t)Dd*Ee/2];      // Wg1^T as half2: [n=64][k]

__device__ __forceinline__ float head_slope(int h) {
    return exp2f(-0.5f * (float)(h + 1)) * 1.00001f;
}
__device__ __forceinline__ float silu_f(float v) { return v / (1.0f + expf(-v)); }
__device__ __forceinline__ uint32_t s2u(const void* p) {
    return (uint32_t)__cvta_generic_to_shared(p);
}
__device__ __forceinline__ uint32_t packh2(float a, float b) {
    __half2 h = __floats2half2_rn(a, b);
    return *(uint32_t*)&h;
}

#define CP16(dst, src) \
    asm volatile("cp.async.cg.shared.global [%0], [%1], 16;" :: "r"(dst), "l"(src) : "memory")
#define CP_COMMIT() asm volatile("cp.async.commit_group;" ::: "memory")
#define CP_WAIT2()  asm volatile("cp.async.wait_group 2;" ::: "memory")

__device__ __forceinline__ void mma_f16(
    float c[4], const uint32_t a[4], const uint32_t b[2])
{
    asm volatile(
        "mma.sync.aligned.m16n8k16.row.col.f32.f16.f16.f32 "
        "{%0,%1,%2,%3}, {%4,%5,%6,%7}, {%8,%9}, {%0,%1,%2,%3};"
        : "+f"(c[0]), "+f"(c[1]), "+f"(c[2]), "+f"(c[3])
        : "r"(a[0]), "r"(a[1]), "r"(a[2]), "r"(a[3]),
          "r"(b[0]), "r"(b[1]));
}

// ============================================================
// Conversion kernels
// ============================================================
__global__ __launch_bounds__(256) void conv_x(const float* __restrict__ x)
{
    size_t i = (size_t)(blockIdx.x * 256 + threadIdx.x);
    const size_t n4 = (size_t)Mm * Ee / 4;
    const size_t stride = (size_t)gridDim.x * 256;
    for (; i < n4; i += stride) {
        float4 v = ((const float4*)x)[i];
        uint2 u;
        u.x = packh2(v.x, v.y);
        u.y = packh2(v.z, v.w);
        ((uint2*)g_xh)[i] = u;
    }
}

// W[k][n] -> WT[n][k] half.  grid (32, 32, 4), 256 thr
__global__ __launch_bounds__(256) void conv_wt(
    const float* __restrict__ Wq, const float* __restrict__ Wk,
    const float* __restrict__ Wv, const float* __restrict__ Wo)
{
    __shared__ float t[32][33];
    const float* W = (blockIdx.z == 0) ? Wq : (blockIdx.z == 1) ? Wk :
                     (blockIdx.z == 2) ? Wv : Wo;
    __half* WT = (__half*)g_Wh[blockIdx.z];
    const int tx = threadIdx.x & 31;
    const int ty = threadIdx.x >> 5;     // 0..7
    const int n0 = blockIdx.x * 32;      // n tile
    const int k0 = blockIdx.y * 32;      // k tile
#pragma unroll
    for (int j = 0; j < 32; j += 8)
        t[ty + j][tx] = W[(size_t)(k0 + ty + j) * Ee + n0 + tx];
    __syncthreads();
#pragma unroll
    for (int j = 0; j < 32; j += 8)
        WT[(size_t)(n0 + ty + j) * Ee + k0 + tx] = __float2half_rn(t[tx][ty + j]);
}

// Wg1[k][64] -> Wg1T[n][k] half.  grid (2, 32), 256 thr
__global__ __launch_bounds__(256) void conv_wg1(const float* __restrict__ Wg1)
{
    __shared__ float t[32][33];
    __half* WT = (__half*)g_Wg1h;
    const int tx = threadIdx.x & 31;
    const int ty = threadIdx.x >> 5;
    const int n0 = blockIdx.x * 32;
    const int k0 = blockIdx.y * 32;
#pragma unroll
    for (int j = 0; j < 32; j += 8)
        t[ty + j][tx] = Wg1[(size_t)(k0 + ty + j) * Dd + n0 + tx];
    __syncthreads();
#pragma unroll
    for (int j = 0; j < 32; j += 8)
        WT[(size_t)(n0 + ty + j) * Ee + k0 + tx] = __float2half_rn(t[tx][ty + j]);
}

// ============================================================
// fp16 mma.sync GEMM, 4-stage cp.async pipeline.
// A: [M][k] half2-packed rows; B: [N][k] half2-packed rows (W^T).
// CTA tile 128 x (NB); 8 warps (4m x 2n), warp tile 32 x NI*8.
// smem rows: [row][20] uint32 (32 halves + pad) -> conflict-free frags.
// Per stage: BK=32 halves (16 uint32), 2 k-blocks of m16n8k16.
// ============================================================
#define ROWU 20
#define STGH 4

template<int NB, int NI>
__device__ __forceinline__ void gemm_core_f16(
    const uint32_t* __restrict__ A, const uint32_t* __restrict__ Bm,
    float* __restrict__ C, int brow, int bcol, int act, int ldc)
{
    extern __shared__ uint32_t smem[];
    const int stageA = 128 * ROWU;
    const int stageB = NB * ROWU;
    uint32_t* As0 = smem;
    uint32_t* Bs0 = smem + STGH * stageA;

    const int tid  = threadIdx.x;
    const int wid  = tid >> 5;
    const int lane = tid & 31;
    const int g = lane >> 2, t = lane & 3;
    const int wm = (wid & 3) * 32;
    const int wn = (wid >> 2) * (NI * 8);

    // G2S plan: each cp = 16B = 4 uint32 (8 halves); 4 cps per 128-row... per row.
    // A: 512 cps/stage (2 per thread). B: NB*4 cps/stage.
    const int ar0 = tid >> 2, ap0 = (tid & 3) * 4;           // idx = tid
    const int ar1 = (tid + 256) >> 2, ap1 = ap0;             // idx = tid+256
    const uint32_t* Ag0 = A + (size_t)(brow + ar0) * 512 + ap0;
    const uint32_t* Ag1 = A + (size_t)(brow + ar1) * 512 + ap1;
    const uint32_t dA0 = s2u(As0 + (size_t)ar0 * ROWU + ap0);
    const uint32_t dA1 = s2u(As0 + (size_t)ar1 * ROWU + ap1);

    const int br0 = tid >> 2, bp0 = (tid & 3) * 4;
    const uint32_t* Bg0 = Bm + (size_t)(bcol + br0) * 512 + bp0;
    const uint32_t dB0 = s2u(Bs0 + (size_t)br0 * ROWU + bp0);
    // second B cp only when NB==128
    const int br1 = (tid + 256) >> 2;
    const uint32_t* Bg1 = Bm + (size_t)(bcol + br1) * 512 + bp0;
    const uint32_t dB1 = s2u(Bs0 + (size_t)br1 * ROWU + bp0);

    const uint32_t sA = stageA * 4;   // stage stride bytes
    const uint32_t sB = stageB * 4;

    float acc[2][NI][4];
#pragma unroll
    for (int mi = 0; mi < 2; mi++)
#pragma unroll
        for (int ni = 0; ni < NI; ni++)
#pragma unroll
            for (int j = 0; j < 4; j++) acc[mi][ni][j] = 0.0f;

    // prologue: stages 0..2
#pragma unroll
    for (int p = 0; p < 3; p++) {
        CP16(dA0 + p * sA, Ag0 + p * 16);
        CP16(dA1 + p * sA, Ag1 + p * 16);
        CP16(dB0 + p * sB, Bg0 + p * 16);
        if (NB == 128) CP16(dB1 + p * sB, Bg1 + p * 16);
        CP_COMMIT();
    }

    for (int c = 0; c < 32; c++) {
        CP_WAIT2();
        __syncthreads();

        if (c + 3 < 32) {
            const int s = (c + 3) & 3;
            CP16(dA0 + s * sA, Ag0 + (c + 3) * 16);
            CP16(dA1 + s * sA, Ag1 + (c + 3) * 16);
            CP16(dB0 + s * sB, Bg0 + (c + 3) * 16);
            if (NB == 128) CP16(dB1 + s * sB, Bg1 + (c + 3) * 16);
            CP_COMMIT();
        }

        const uint32_t* As = As0 + (size_t)(c & 3) * stageA;
        const uint32_t* Bs = Bs0 + (size_t)(c & 3) * stageB;

#pragma unroll
        for (int kb = 0; kb < 2; kb++) {
            const int ko = kb * 8;
            uint32_t afr[2][4], bfr[NI][2];
#pragma unroll
            for (int mi = 0; mi < 2; mi++) {
                const int m = wm + mi * 16 + g;
                afr[mi][0] = As[(size_t)m * ROWU + ko + t];
                afr[mi][1] = As[(size_t)(m + 8) * ROWU + ko + t];
                afr[mi][2] = As[(size_t)m * ROWU + ko + t + 4];
                afr[mi][3] = As[(size_t)(m + 8) * ROWU + ko + t + 4];
            }
#pragma unroll
            for (int ni = 0; ni < NI; ni++) {
                const int n = wn + ni * 8 + g;
                bfr[ni][0] = Bs[(size_t)n * ROWU + ko + t];
                bfr[ni][1] = Bs[(size_t)n * ROWU + ko + t + 4];
            }
#pragma unroll
            for (int mi = 0; mi < 2; mi++)
#pragma unroll
                for (int ni = 0; ni < NI; ni++)
                    mma_f16(acc[mi][ni], afr[mi], bfr[ni]);
        }
    }

    // epilogue (c0,c1 = row g cols 2t,2t+1; c2,c3 = row g+8)
#pragma unroll
    for (int mi = 0; mi < 2; mi++) {
        const int r0 = brow + wm + mi * 16 + g;
#pragma unroll
        for (int ni = 0; ni < NI; ni++) {
            const int col = bcol + wn + ni * 8 + 2 * t;
            float v0 = acc[mi][ni][0], v1 = acc[mi][ni][1];
            float v2 = acc[mi][ni][2], v3 = acc[mi][ni][3];
            if (act) { v0 = silu_f(v0); v1 = silu_f(v1); v2 = silu_f(v2); v3 = silu_f(v3); }
            float2 lo; lo.x = v0; lo.y = v1;
            float2 hi; hi.x = v2; hi.y = v3;
            *(float2*)(C + (size_t)r0 * ldc + col) = lo;
            *(float2*)(C + (size_t)(r0 + 8) * ldc + col) = hi;
        }
    }
}

#define GEMM_SMEM_BIG (STGH * (128*ROWU + 128*ROWU) * 4)
#define GEMM_SMEM_G1  (STGH * (128*ROWU + 64*ROWU) * 4)

__global__ __launch_bounds__(256) void gemm_qkv_f16()
{
    float* C = (blockIdx.z == 0) ? g_q : (blockIdx.z == 1) ? g_k : g_v;
    gemm_core_f16<128, 8>(g_xh, g_Wh[blockIdx.z], C,
                          blockIdx.y * 128, blockIdx.x * 128, 1, Ee);
}

__global__ __launch_bounds__(256) void gemm_out_f16(float* __restrict__ C)
{
    gemm_core_f16<128, 8>(g_uh, g_Wh[3], C,
                          blockIdx.y * 128, blockIdx.x * 128, 0, Ee);
}

__global__ __launch_bounds__(256) void gemm_g1_f16()
{
    gemm_core_f16<64, 4>(g_xh, g_Wg1h, g_g1,
                         blockIdx.x * 128, 0, 0, Dd);
}

// ============================================================
// Intra-chunk attention + per-chunk kv contribution A_c (fp32)
// ============================================================
#define SM_QT   0
#define SM_KT   (64*132)
#define SM_VS   (2*64*132)
#define SM_SS   (2*64*132 + 128*68)
#define SM_LAM  (2*64*132 + 128*68 + 128*129)
#define SMEM_INTRA_FLOATS (2*64*132 + 128*68 + 128*129 + 128)

__global__ __launch_bounds__(256) void attn_intra(
    const float* __restrict__ q, const float* __restrict__ k,
    const float* __restrict__ v)
{
    extern __shared__ float sm[];
    float* qT  = sm + SM_QT;
    float* kT  = sm + SM_KT;
    float* vs  = sm + SM_VS;
    float* Ss  = sm + SM_SS;
    float* lamk = sm + SM_LAM;

    const int c = blockIdx.x, h = blockIdx.y, b = blockIdx.z;
    const int tid = threadIdx.x;
    const float s = head_slope(h);
    const size_t base = ((size_t)b * Nn + (size_t)c * Cc) * Ee + (size_t)h * Dd;

#pragma unroll
    for (int t = 0; t < 8; t++) {
        int e = tid + t * 256;
        int row = e >> 4;
        int d4 = (e & 15) * 4;
        const size_t g = base + (size_t)row * Ee + d4;
        float4 qv = *(const float4*)(q + g);
        qT[(d4 + 0) * 132 + row] = qv.x;
        qT[(d4 + 1) * 132 + row] = qv.y;
        qT[(d4 + 2) * 132 + row] = qv.z;
        qT[(d4 + 3) * 132 + row] = qv.w;
        float4 kv4 = *(const float4*)(k + g);
        kT[(d4 + 0) * 132 + row] = kv4.x;
        kT[(d4 + 1) * 132 + row] = kv4.y;
        kT[(d4 + 2) * 132 + row] = kv4.z;
        kT[(d4 + 3) * 132 + row] = kv4.w;
        *(float4*)&vs[row * 68 + d4] = *(const float4*)(v + g);
    }
    if (tid < 128) lamk[tid] = expf(-s * (float)(Cc - 1 - tid));
    __syncthreads();

    const int tx = tid & 15, ty = tid >> 4;

    float acc[8][8];
#pragma unroll
    for (int i = 0; i < 8; i++)
#pragma unroll
        for (int j = 0; j < 8; j++) acc[i][j] = 0.0f;

    for (int d = 0; d < 64; d++) {
        float af[8], bf[8];
        *(float4*)&af[0] = *(float4*)&qT[d * 132 + ty * 8];
        *(float4*)&af[4] = *(float4*)&qT[d * 132 + ty * 8 + 4];
        *(float4*)&bf[0] = *(float4*)&kT[d * 132 + tx * 8];
        *(float4*)&bf[4] = *(float4*)&kT[d * 132 + tx * 8 + 4];
#pragma unroll
        for (int i = 0; i < 8; i++)
#pragma unroll
            for (int j = 0; j < 8; j++)
                acc[i][j] = fmaf(af[i], bf[j], acc[i][j]);
    }
#pragma unroll
    for (int ii = 0; ii < 8; ii++) {
        int i = ty * 8 + ii;
#pragma unroll
        for (int jj = 0; jj < 8; jj++) {
            int j = tx * 8 + jj;
            float val = 0.0f;
            if (i >= j) val = acc[ii][jj] * expf(-s * (float)(i - j));
            Ss[i * 129 + j] = val;
        }
    }
    __syncthreads();

    float oc[8][4];
#pragma unroll
    for (int i = 0; i < 8; i++)
#pragma unroll
        for (int j = 0; j < 4; j++) oc[i][j] = 0.0f;

    for (int j = 0; j < 128; j++) {
        float bv[4];
        *(float4*)bv = *(float4*)&vs[j * 68 + tx * 4];
#pragma unroll
        for (int ii = 0; ii < 8; ii++) {
            float a = Ss[(ty * 8 + ii) * 129 + j];
#pragma unroll
            for (int dd = 0; dd < 4; dd++)
                oc[ii][dd] = fmaf(a, bv[dd], oc[ii][dd]);
        }
    }
#pragma unroll
    for (int ii = 0; ii < 8; ii++) {
        float4 o;
        o.x = oc[ii][0]; o.y = oc[ii][1]; o.z = oc[ii][2]; o.w = oc[ii][3];
        *(float4*)(g_o + base + (size_t)(ty * 8 + ii) * Ee + tx * 4) = o;
    }

    float ac[4][4];
#pragma unroll
    for (int i = 0; i < 4; i++)
#pragma unroll
        for (int j = 0; j < 4; j++) ac[i][j] = 0.0f;

    const int dr = ty * 4;
    for (int j = 0; j < 128; j++) {
        float lam = lamk[j];
        float bv[4];
        *(float4*)bv = *(float4*)&vs[j * 68 + tx * 4];
#pragma unroll
        for (int i = 0; i < 4; i++) {
            float a = kT[(dr + i) * 132 + j] * lam;
#pragma unroll
            for (int e2 = 0; e2 < 4; e2++)
                ac[i][e2] = fmaf(a, bv[e2], ac[i][e2]);
        }
    }
    float* Ab = g_A + ((((size_t)b * Hh + h) * NCk + c) * (Dd * Dd));
#pragma unroll
    for (int i = 0; i < 4; i++) {
        float4 o;
        o.x = ac[i][0]; o.y = ac[i][1]; o.z = ac[i][2]; o.w = ac[i][3];
        *(float4*)&Ab[(dr + i) * Dd + tx * 4] = o;
    }
}

// ============================================================
// kv prefix scan: one (b,h,element) chain per thread
// ============================================================
__global__ __launch_bounds__(256) void kv_scan()
{
    const int gidx = blockIdx.x * 256 + threadIdx.x;
    const int bh = gidx >> 12;
    const int e  = gidx & 4095;
    const int h  = bh & 15;
    const float s = head_slope(h);
    const float lamc = expf(-s * (float)Cc);

    size_t off = (size_t)bh * NCk * (Dd * Dd) + e;
    float kv = 0.0f;
#pragma unroll 4
    for (int c = 0; c < NCk; c++) {
        g_kv[off] = kv;
        kv = fmaf(lamc, kv, g_A[off]);
        off += Dd * Dd;
    }
}

// ============================================================
// Inter-chunk: o += lam_q[i] * (q @ kv_prefix)
// ============================================================
#define SMEM_INTER_FLOATS (128*68 + 64*68)

__global__ __launch_bounds__(256) void attn_inter(const float* __restrict__ q)
{
    extern __shared__ float sm[];
    float* qs  = sm;
    float* kvs = sm + 128 * 68;

    const int c = blockIdx.x, h = blockIdx.y, b = blockIdx.z;
    const int tid = threadIdx.x;
    const float s = head_slope(h);
    const size_t base = ((size_t)b * Nn + (size_t)c * Cc) * Ee + (size_t)h * Dd;

#pragma unroll
    for (int t = 0; t < 8; t++) {
        int e = tid + t * 256;
        int row = e >> 4;
        int d4 = (e & 15) * 4;
        *(float4*)&qs[row * 68 + d4] = *(const float4*)(q + base + (size_t)row * Ee + d4);
    }
    const float* kvp = g_kv + (((size_t)b * Hh + h) * NCk + c) * (Dd * Dd);
#pragma unroll
    for (int t = 0; t < 4; t++) {
        int e = tid + t * 256;
        int row = e >> 4;
        int d4 = (e & 15) * 4;
        *(float4*)&kvs[row * 68 + d4] = *(const float4*)(kvp + row * Dd + d4);
    }
    __syncthreads();

    const int tx = tid & 15, ty = tid >> 4;
    float oc[8][4];
#pragma unroll
    for (int i = 0; i < 8; i++)
#pragma unroll
        for (int j = 0; j < 4; j++) oc[i][j] = 0.0f;

    for (int e2 = 0; e2 < 64; e2++) {
        float bv[4];
        *(float4*)bv = *(float4*)&kvs[e2 * 68 + tx * 4];
#pragma unroll
        for (int ii = 0; ii < 8; ii++) {
            float a = qs[(ty * 8 + ii) * 68 + e2];
#pragma unroll
            for (int dd = 0; dd < 4; dd++)
                oc[ii][dd] = fmaf(a, bv[dd], oc[ii][dd]);
        }
    }
#pragma unroll
    for (int ii = 0; ii < 8; ii++) {
        int i = ty * 8 + ii;
        float lamq = expf(-s * (float)(i + 1));
        float* op = g_o + base + (size_t)i * Ee + tx * 4;
        float4 prev = *(float4*)op;
        prev.x = fmaf(lamq, oc[ii][0], prev.x);
        prev.y = fmaf(lamq, oc[ii][1], prev.y);
        prev.z = fmaf(lamq, oc[ii][2], prev.z);
        prev.w = fmaf(lamq, oc[ii][3], prev.w);
        *(float4*)op = prev;
    }
}

// ============================================================
// LayerNorm + gate (g1 @ Wg2 -> sigmoid) + multiply -> g_uh (half)
// ============================================================
__global__ __launch_bounds__(256) void ln_gate(
    const float* __restrict__ gamma, const float* __restrict__ beta,
    const float* __restrict__ Wg2)
{
    __shared__ float os[8 * 1024];
    __shared__ float g1s[8 * 64];
    __shared__ float wsum[8], wsq[8];
    __shared__ float mu_s[8], rs_s[8];

    const int tid = threadIdx.x;
    const size_t row0 = (size_t)blockIdx.x * 8;

#pragma unroll
    for (int t = 0; t < 8; t++) {
        int e = tid + t * 256;
        int r = e >> 8;
        int c4 = (e & 255) * 4;
        *(float4*)&os[r * 1024 + c4] = *(const float4*)(g_o + (row0 + r) * 1024 + c4);
    }
    if (tid < 128) {
        int r = tid >> 4;
        int c4 = (tid & 15) * 4;
        *(float4*)&g1s[r * 64 + c4] = *(const float4*)(g_g1 + (row0 + r) * 64 + c4);
    }
    __syncthreads();

    const int lane = tid & 31, wid = tid >> 5;

    for (int r = 0; r < 8; r++) {
        float sum = 0.0f;
#pragma unroll
        for (int t = 0; t < 4; t++) sum += os[r * 1024 + tid + t * 256];
#pragma unroll
        for (int o = 16; o; o >>= 1) sum += __shfl_xor_sync(0xffffffffu, sum, o);
        if (lane == 0) wsum[wid] = sum;
        __syncthreads();
        if (tid == 0) {
            float S = 0.0f;
            for (int w = 0; w < 8; w++) S += wsum[w];
            mu_s[r] = S * (1.0f / 1024.0f);
        }
        __syncthreads();
    }
    for (int r = 0; r < 8; r++) {
        float mu = mu_s[r];
        float sq = 0.0f;
#pragma unroll
        for (int t = 0; t < 4; t++) {
            float d = os[r * 1024 + tid + t * 256] - mu;
            sq = fmaf(d, d, sq);
        }
#pragma unroll
        for (int o = 16; o; o >>= 1) sq += __shfl_xor_sync(0xffffffffu, sq, o);
        if (lane == 0) wsq[wid] = sq;
        __syncthreads();
        if (tid == 0) {
            float Q = 0.0f;
            for (int w = 0; w < 8; w++) Q += wsq[w];
            rs_s[r] = rsqrtf(Q * (1.0f / 1024.0f) + 1e-5f);
        }
        __syncthreads();
    }

    const int r = wid;
    const int cbase = lane * 4;
    const float mu = mu_s[r];
    const float rs = rs_s[r];
#pragma unroll
    for (int t = 0; t < 8; t++) {
        int col = cbase + t * 128;
        float4 ov = *(float4*)&os[r * 1024 + col];
        float4 gd = make_float4(0, 0, 0, 0);
        for (int kk = 0; kk < 64; kk++) {
            float gk = g1s[r * 64 + kk];
            float4 w = *(const float4*)(Wg2 + (size_t)kk * 1024 + col);
            gd.x = fmaf(gk, w.x, gd.x);
            gd.y = fmaf(gk, w.y, gd.y);
            gd.z = fmaf(gk, w.z, gd.z);
            gd.w = fmaf(gk, w.w, gd.w);
        }
        float4 gm = *(const float4*)(gamma + col);
        float4 bt = *(const float4*)(beta + col);
        float ux = (fmaf((ov.x - mu) * rs, gm.x, bt.x)) * (1.0f / (1.0f + expf(-gd.x)));
        float uy = (fmaf((ov.y - mu) * rs, gm.y, bt.y)) * (1.0f / (1.0f + expf(-gd.y)));
        float uz = (fmaf((ov.z - mu) * rs, gm.z, bt.z)) * (1.0f / (1.0f + expf(-gd.z)));
        float uw = (fmaf((ov.w - mu) * rs, gm.w, bt.w)) * (1.0f / (1.0f + expf(-gd.w)));
        uint2 u;
        u.x = packh2(ux, uy);
        u.y = packh2(uz, uw);
        *(uint2*)(g_uh + ((row0 + r) * 1024 + col) / 2) = u;
    }
}

// ============================================================
// host launch
// ============================================================
extern "C" void kernel_launch(void* const* d_in, const int* in_sizes, int n_in,
                              void* d_out, int out_size)
{
    const float* x     = (const float*)d_in[0];
    const float* Wq    = (const float*)d_in[1];
    const float* Wk    = (const float*)d_in[2];
    const float* Wv    = (const float*)d_in[3];
    const float* Wo    = (const float*)d_in[4];
    const float* gamma = (const float*)d_in[5];
    const float* beta  = (const float*)d_in[6];
    const float* Wg1   = (const float*)d_in[7];
    const float* Wg2   = (const float*)d_in[8];
    float* out = (float*)d_out;

    static bool init_done = false;
    static float *qp, *kp, *vp;
    if (!init_done) {
        cudaGetSymbolAddress((void**)&qp, g_q);
        cudaGetSymbolAddress((void**)&kp, g_k);
        cudaGetSymbolAddress((void**)&vp, g_v);
        cudaFuncSetAttribute(attn_intra, cudaFuncAttributeMaxDynamicSharedMemorySize,
                             SMEM_INTRA_FLOATS * (int)sizeof(float));
        cudaFuncSetAttribute(attn_inter, cudaFuncAttributeMaxDynamicSharedMemorySize,
                             SMEM_INTER_FLOATS * (int)sizeof(float));
        cudaFuncSetAttribute(gemm_qkv_f16, cudaFuncAttributeMaxDynamicSharedMemorySize,
                             GEMM_SMEM_BIG);
        cudaFuncSetAttribute(gemm_out_f16, cudaFuncAttributeMaxDynamicSharedMemorySize,
                             GEMM_SMEM_BIG);
        cudaFuncSetAttribute(gemm_g1_f16, cudaFuncAttributeMaxDynamicSharedMemorySize,
                             GEMM_SMEM_G1);
        init_done = true;
    }

    const int smem_intra = SMEM_INTRA_FLOATS * (int)sizeof(float);
    const int smem_inter = SMEM_INTER_FLOATS * (int)sizeof(float);

    dim3 blk(256);

    conv_x<<<4096, blk>>>(x);
    conv_wt<<<dim3(32, 32, 4), blk>>>(Wq, Wk, Wv, Wo);
    conv_wg1<<<dim3(2, 32), blk>>>(Wg1);

    gemm_qkv_f16<<<dim3(Ee / 128, Mm / 128, 3), blk, GEMM_SMEM_BIG>>>();
    gemm_g1_f16<<<Mm / 128, blk, GEMM_SMEM_G1>>>();

    attn_intra<<<dim3(NCk, Hh, Bb), blk, smem_intra>>>(qp, kp, vp);
    kv_scan<<<512, blk>>>();
    attn_inter<<<dim3(NCk, Hh, Bb), blk, smem_inter>>>(qp);

    ln_gate<<<Mm / 8, blk>>>(gamma, beta, Wg2);

    gemm_out_f16<<<dim3(Ee / 128, Mm / 128), blk, GEMM_SMEM_BIG>>>(out);
}

// round 9
// speedup vs baseline: 3.5977x; 1.1298x over previous
#include <cuda_runtime.h>
#include <cuda_fp16.h>
#include <math.h>
#include <stdint.h>

// ---------------- problem constants ----------------
#define Bb   2
#define Nn   8192
#define Ee   1024
#define Hh   16
#define Dd   64
#define Cc   128
#define NCk  64
#define Mm   (Bb*Nn)

// ---------------- device scratch ----------------
__device__ float g_q[(size_t)Mm*Ee];
__device__ float g_k[(size_t)Mm*Ee];
__device__ float g_v[(size_t)Mm*Ee];
__device__ float g_o[(size_t)Mm*Ee];
__device__ float g_A [(size_t)Bb*Hh*NCk*Dd*Dd];
__device__ float g_kv[(size_t)Bb*Hh*NCk*Dd*Dd];
__device__ float g_g1[(size_t)Mm*Dd];
__device__ float g_gd[(size_t)Mm*Ee];             // gate pre-sigmoid = g1 @ Wg2
__device__ uint32_t g_xh[(size_t)Mm*Ee/2];        // x half2, [m][k] K-PERMUTED
__device__ uint32_t g_uh[(size_t)Mm*Ee/2];        // LN-gate out half2, K-PERMUTED
__device__ uint32_t g_Wh[4][(size_t)Ee*Ee/2];     // W^T half2: [n][k] K-PERMUTED
__device__ uint32_t g_Wg1h[(size_t)Dd*Ee/2];      // Wg1^T half2: [n=64][k] K-PERMUTED

// K-permutation within each 16-uint32 (32-half) block:
//   new[4j+i] = orig[j+4i]  (j,i in 0..3)
// => thread t's fragment need {orig t, t+4, t+8, t+12} = new[4t..4t+3] (one LDS.128)
__device__ __forceinline__ int knew(int o) {      // orig uint32 idx -> new uint32 idx
    return (o & ~15) + 4 * (o & 3) + ((o & 15) >> 2);
}

__device__ __forceinline__ float head_slope(int h) {
    return exp2f(-0.5f * (float)(h + 1)) * 1.00001f;
}
__device__ __forceinline__ float silu_f(float v) { return v / (1.0f + expf(-v)); }
__device__ __forceinline__ uint32_t s2u(const void* p) {
    return (uint32_t)__cvta_generic_to_shared(p);
}
__device__ __forceinline__ uint32_t packh2(float a, float b) {
    __half2 h = __floats2half2_rn(a, b);
    return *(uint32_t*)&h;
}

#define CP16(dst, src) \
    asm volatile("cp.async.cg.shared.global [%0], [%1], 16;" :: "r"(dst), "l"(src) : "memory")
#define CP_COMMIT() asm volatile("cp.async.commit_group;" ::: "memory")
#define CP_WAIT2()  asm volatile("cp.async.wait_group 2;" ::: "memory")

__device__ __forceinline__ void mma_f16(
    float c[4], uint32_t a0, uint32_t a1, uint32_t a2, uint32_t a3,
    uint32_t b0, uint32_t b1)
{
    asm volatile(
        "mma.sync.aligned.m16n8k16.row.col.f32.f16.f16.f32 "
        "{%0,%1,%2,%3}, {%4,%5,%6,%7}, {%8,%9}, {%0,%1,%2,%3};"
        : "+f"(c[0]), "+f"(c[1]), "+f"(c[2]), "+f"(c[3])
        : "r"(a0), "r"(a1), "r"(a2), "r"(a3), "r"(b0), "r"(b1));
}

// ============================================================
// Conversion kernels (emit K-PERMUTED layouts)
// ============================================================
__global__ __launch_bounds__(256) void conv_x(const float* __restrict__ x)
{
    size_t f = (size_t)(blockIdx.x * 256 + threadIdx.x);    // float4 index
    const size_t n4 = (size_t)Mm * Ee / 4;
    const size_t stride = (size_t)gridDim.x * 256;
    for (; f < n4; f += stride) {
        float4 v = ((const float4*)x)[f];
        int o0 = (int)(f * 2) & 511;            // orig uint32 idx within row (rows=512 u32)
        size_t rowbase = (f * 2) & ~(size_t)511;
        g_xh[rowbase + knew(o0)]     = packh2(v.x, v.y);
        g_xh[rowbase + knew(o0 + 1)] = packh2(v.z, v.w);
    }
}

// W[k][n] -> WT[n][k] half, K-permuted.  grid (32, 32, 4), 256 thr
__global__ __launch_bounds__(256) void conv_wt(
    const float* __restrict__ Wq, const float* __restrict__ Wk,
    const float* __restrict__ Wv, const float* __restrict__ Wo)
{
    __shared__ float t[32][33];
    const float* W = (blockIdx.z == 0) ? Wq : (blockIdx.z == 1) ? Wk :
                     (blockIdx.z == 2) ? Wv : Wo;
    __half* WT = (__half*)g_Wh[blockIdx.z];
    const int tx = threadIdx.x & 31;
    const int ty = threadIdx.x >> 5;
    const int n0 = blockIdx.x * 32;
    const int k0 = blockIdx.y * 32;
#pragma unroll
    for (int j = 0; j < 32; j += 8)
        t[ty + j][tx] = W[(size_t)(k0 + ty + j) * Ee + n0 + tx];
    __syncthreads();
#pragma unroll
    for (int j = 0; j < 32; j += 8) {
        int k = k0 + tx;
        int kk = knew(k >> 1) * 2 + (k & 1);    // permuted half index
        WT[(size_t)(n0 + ty + j) * Ee + kk] = __float2half_rn(t[tx][ty + j]);
    }
}

// Wg1[k][64] -> Wg1T[n][k] half, K-permuted.  grid (2, 32), 256 thr
__global__ __launch_bounds__(256) void conv_wg1(const float* __restrict__ Wg1)
{
    __shared__ float t[32][33];
    __half* WT = (__half*)g_Wg1h;
    const int tx = threadIdx.x & 31;
    const int ty = threadIdx.x >> 5;
    const int n0 = blockIdx.x * 32;
    const int k0 = blockIdx.y * 32;
#pragma unroll
    for (int j = 0; j < 32; j += 8)
        t[ty + j][tx] = Wg1[(size_t)(k0 + ty + j) * Dd + n0 + tx];
    __syncthreads();
#pragma unroll
    for (int j = 0; j < 32; j += 8) {
        int k = k0 + tx;
        int kk = knew(k >> 1) * 2 + (k & 1);
        WT[(size_t)(n0 + ty + j) * Ee + kk] = __float2half_rn(t[tx][ty + j]);
    }
}

// ============================================================
// fp16 mma.sync GEMM, 4-stage cp.async pipeline, LDS.128 frags
// via K-permuted layout. Rows: 16 uint32, NO pad (64B stride ->
// frag LDS.128 and cp.async writes both phase-conflict-free).
// ============================================================
#define RU 16
#define STGH 4

template<int NB, int NI>
__device__ __forceinline__ void gemm_core_f16(
    const uint32_t* __restrict__ A, const uint32_t* __restrict__ Bm,
    float* __restrict__ C, int brow, int bcol, int act, int ldc)
{
    extern __shared__ uint32_t smem[];
    const int stageA = 128 * RU;
    const int stageB = NB * RU;
    uint32_t* As0 = smem;
    uint32_t* Bs0 = smem + STGH * stageA;

    const int tid  = threadIdx.x;
    const int wid  = tid >> 5;
    const int lane = tid & 31;
    const int g = lane >> 2, t = lane & 3;
    const int wm = (wid & 3) * 32;
    const int wn = (wid >> 2) * (NI * 8);

    // ---- G2S plan (16B per cp) ----
    const int ar0 = tid >> 2, ap0 = (tid & 3) * 4;
    const int ar1 = (tid + 256) >> 2;
    const uint32_t* Ag0 = A + (size_t)(brow + ar0) * 512 + ap0;
    const uint32_t* Ag1 = A + (size_t)(brow + ar1) * 512 + ap0;
    const uint32_t dA0 = s2u(As0 + (size_t)ar0 * RU + ap0);
    const uint32_t dA1 = s2u(As0 + (size_t)ar1 * RU + ap0);

    const uint32_t* Bg0 = Bm + (size_t)(bcol + ar0) * 512 + ap0;
    const uint32_t dB0 = s2u(Bs0 + (size_t)ar0 * RU + ap0);
    const uint32_t* Bg1 = Bm + (size_t)(bcol + ar1) * 512 + ap0;
    const uint32_t dB1 = s2u(Bs0 + (size_t)ar1 * RU + ap0);

    const uint32_t sA = stageA * 4;
    const uint32_t sB = stageB * 4;

    float acc[2][NI][4];
#pragma unroll
    for (int mi = 0; mi < 2; mi++)
#pragma unroll
        for (int ni = 0; ni < NI; ni++)
#pragma unroll
            for (int j = 0; j < 4; j++) acc[mi][ni][j] = 0.0f;

#pragma unroll
    for (int p = 0; p < 3; p++) {
        CP16(dA0 + p * sA, Ag0 + p * 16);
        CP16(dA1 + p * sA, Ag1 + p * 16);
        CP16(dB0 + p * sB, Bg0 + p * 16);
        if (NB == 128) CP16(dB1 + p * sB, Bg1 + p * 16);
        CP_COMMIT();
    }

    for (int c = 0; c < 32; c++) {
        CP_WAIT2();
        __syncthreads();

        if (c + 3 < 32) {
            const int s = (c + 3) & 3;
            CP16(dA0 + s * sA, Ag0 + (c + 3) * 16);
            CP16(dA1 + s * sA, Ag1 + (c + 3) * 16);
            CP16(dB0 + s * sB, Bg0 + (c + 3) * 16);
            if (NB == 128) CP16(dB1 + s * sB, Bg1 + (c + 3) * 16);
            CP_COMMIT();
        }

        const uint32_t* As = As0 + (size_t)(c & 3) * stageA;
        const uint32_t* Bs = Bs0 + (size_t)(c & 3) * stageB;

        // frag loads: one LDS.128 per row (contains both k-blocks)
        uint4 Af[2][2];   // [mi][row: m / m+8]
#pragma unroll
        for (int mi = 0; mi < 2; mi++) {
            const int m = wm + mi * 16 + g;
            Af[mi][0] = *(const uint4*)&As[(size_t)m * RU + 4 * t];
            Af[mi][1] = *(const uint4*)&As[(size_t)(m + 8) * RU + 4 * t];
        }
        uint4 Bf[NI];
#pragma unroll
        for (int ni = 0; ni < NI; ni++) {
            const int n = wn + ni * 8 + g;
            Bf[ni] = *(const uint4*)&Bs[(size_t)n * RU + 4 * t];
        }

        // k-block 0: (x,y) components; k-block 1: (z,w)
#pragma unroll
        for (int mi = 0; mi < 2; mi++)
#pragma unroll
            for (int ni = 0; ni < NI; ni++)
                mma_f16(acc[mi][ni],
                        Af[mi][0].x, Af[mi][1].x, Af[mi][0].y, Af[mi][1].y,
                        Bf[ni].x, Bf[ni].y);
#pragma unroll
        for (int mi = 0; mi < 2; mi++)
#pragma unroll
            for (int ni = 0; ni < NI; ni++)
                mma_f16(acc[mi][ni],
                        Af[mi][0].z, Af[mi][1].z, Af[mi][0].w, Af[mi][1].w,
                        Bf[ni].z, Bf[ni].w);
    }

    // epilogue
#pragma unroll
    for (int mi = 0; mi < 2; mi++) {
        const int r0 = brow + wm + mi * 16 + g;
#pragma unroll
        for (int ni = 0; ni < NI; ni++) {
            const int col = bcol + wn + ni * 8 + 2 * t;
            float v0 = acc[mi][ni][0], v1 = acc[mi][ni][1];
            float v2 = acc[mi][ni][2], v3 = acc[mi][ni][3];
            if (act) { v0 = silu_f(v0); v1 = silu_f(v1); v2 = silu_f(v2); v3 = silu_f(v3); }
            float2 lo; lo.x = v0; lo.y = v1;
            float2 hi; hi.x = v2; hi.y = v3;
            *(float2*)(C + (size_t)r0 * ldc + col) = lo;
            *(float2*)(C + (size_t)(r0 + 8) * ldc + col) = hi;
        }
    }
}

#define GEMM_SMEM_BIG (STGH * (128*RU + 128*RU) * 4)
#define GEMM_SMEM_G1  (STGH * (128*RU + 64*RU) * 4)

__global__ __launch_bounds__(256) void gemm_qkv_f16()
{
    float* C = (blockIdx.z == 0) ? g_q : (blockIdx.z == 1) ? g_k : g_v;
    gemm_core_f16<128, 8>(g_xh, g_Wh[blockIdx.z], C,
                          blockIdx.y * 128, blockIdx.x * 128, 1, Ee);
}

__global__ __launch_bounds__(256) void gemm_out_f16(float* __restrict__ C)
{
    gemm_core_f16<128, 8>(g_uh, g_Wh[3], C,
                          blockIdx.y * 128, blockIdx.x * 128, 0, Ee);
}

__global__ __launch_bounds__(256) void gemm_g1_f16()
{
    gemm_core_f16<64, 4>(g_xh, g_Wg1h, g_g1,
                         blockIdx.x * 128, 0, 0, Dd);
}

// ============================================================
// gd = g1 @ Wg2  (fp32 FFMA, exact). M=16384, N=1024, K=64.
// 128x128 tile, 8x8 microtile, grid (8, 128).
// ============================================================
__global__ __launch_bounds__(256) void sgemm_gd(const float* __restrict__ Wg2)
{
    __shared__ float As[2][8][128];
    __shared__ float Bs[2][8][128];

    const float* A = g_g1;
    const int N = Ee, K = Dd;

    const int tid  = threadIdx.x;
    const int tx   = tid & 15;
    const int ty   = tid >> 4;
    const int brow = blockIdx.y * 128;
    const int bcol = blockIdx.x * 128;

    const int arow = tid >> 1;
    const int acol = (tid & 1) * 4;
    const int bkr  = tid >> 5;
    const int bcl  = (tid & 31) * 4;

    const float* Ap = A + (size_t)(brow + arow) * K + acol;
    const float* Bp = Wg2 + (size_t)bkr * N + bcol + bcl;

    float4 ar = *(const float4*)Ap;
    float4 br = *(const float4*)Bp;
    As[0][acol + 0][arow] = ar.x;
    As[0][acol + 1][arow] = ar.y;
    As[0][acol + 2][arow] = ar.z;
    As[0][acol + 3][arow] = ar.w;
    *(float4*)&Bs[0][bkr][bcl] = br;
    __syncthreads();

    float acc[8][8];
#pragma unroll
    for (int i = 0; i < 8; i++)
#pragma unroll
        for (int j = 0; j < 8; j++) acc[i][j] = 0.0f;

    int buf = 0;
    for (int k0 = 8; k0 <= K; k0 += 8) {
        if (k0 < K) {
            ar = *(const float4*)(Ap + k0);
            br = *(const float4*)(Bp + (size_t)k0 * N);
        }
#pragma unroll
        for (int kk = 0; kk < 8; kk++) {
            float af[8], bf[8];
            *(float4*)&af[0] = *(float4*)&As[buf][kk][ty * 8];
            *(float4*)&af[4] = *(float4*)&As[buf][kk][ty * 8 + 4];
            *(float4*)&bf[0] = *(float4*)&Bs[buf][kk][tx * 8];
            *(float4*)&bf[4] = *(float4*)&Bs[buf][kk][tx * 8 + 4];
#pragma unroll
            for (int i = 0; i < 8; i++)
#pragma unroll
                for (int j = 0; j < 8; j++)
                    acc[i][j] = fmaf(af[i], bf[j], acc[i][j]);
        }
        if (k0 < K) {
            buf ^= 1;
            As[buf][acol + 0][arow] = ar.x;
            As[buf][acol + 1][arow] = ar.y;
            As[buf][acol + 2][arow] = ar.z;
            As[buf][acol + 3][arow] = ar.w;
            *(float4*)&Bs[buf][bkr][bcl] = br;
            __syncthreads();
        }
    }

#pragma unroll
    for (int i = 0; i < 8; i++) {
        float* Cp = g_gd + (size_t)(brow + ty * 8 + i) * N + bcol + tx * 8;
#pragma unroll
        for (int j0 = 0; j0 < 8; j0 += 4) {
            float4 o;
            o.x = acc[i][j0 + 0];
            o.y = acc[i][j0 + 1];
            o.z = acc[i][j0 + 2];
            o.w = acc[i][j0 + 3];
            *(float4*)(Cp + j0) = o;
        }
    }
}

// ============================================================
// Intra-chunk attention + per-chunk kv contribution A_c (fp32)
// ============================================================
#define SM_QT   0
#define SM_KT   (64*132)
#define SM_VS   (2*64*132)
#define SM_SS   (2*64*132 + 128*68)
#define SM_LAM  (2*64*132 + 128*68 + 128*129)
#define SMEM_INTRA_FLOATS (2*64*132 + 128*68 + 128*129 + 128)

__global__ __launch_bounds__(256) void attn_intra(
    const float* __restrict__ q, const float* __restrict__ k,
    const float* __restrict__ v)
{
    extern __shared__ float sm[];
    float* qT  = sm + SM_QT;
    float* kT  = sm + SM_KT;
    float* vs  = sm + SM_VS;
    float* Ss  = sm + SM_SS;
    float* lamk = sm + SM_LAM;

    const int c = blockIdx.x, h = blockIdx.y, b = blockIdx.z;
    const int tid = threadIdx.x;
    const float s = head_slope(h);
    const size_t base = ((size_t)b * Nn + (size_t)c * Cc) * Ee + (size_t)h * Dd;

#pragma unroll
    for (int t = 0; t < 8; t++) {
        int e = tid + t * 256;
        int row = e >> 4;
        int d4 = (e & 15) * 4;
        const size_t g = base + (size_t)row * Ee + d4;
        float4 qv = *(const float4*)(q + g);
        qT[(d4 + 0) * 132 + row] = qv.x;
        qT[(d4 + 1) * 132 + row] = qv.y;
        qT[(d4 + 2) * 132 + row] = qv.z;
        qT[(d4 + 3) * 132 + row] = qv.w;
        float4 kv4 = *(const float4*)(k + g);
        kT[(d4 + 0) * 132 + row] = kv4.x;
        kT[(d4 + 1) * 132 + row] = kv4.y;
        kT[(d4 + 2) * 132 + row] = kv4.z;
        kT[(d4 + 3) * 132 + row] = kv4.w;
        *(float4*)&vs[row * 68 + d4] = *(const float4*)(v + g);
    }
    if (tid < 128) lamk[tid] = expf(-s * (float)(Cc - 1 - tid));
    __syncthreads();

    const int tx = tid & 15, ty = tid >> 4;

    float acc[8][8];
#pragma unroll
    for (int i = 0; i < 8; i++)
#pragma unroll
        for (int j = 0; j < 8; j++) acc[i][j] = 0.0f;

    for (int d = 0; d < 64; d++) {
        float af[8], bf[8];
        *(float4*)&af[0] = *(float4*)&qT[d * 132 + ty * 8];
        *(float4*)&af[4] = *(float4*)&qT[d * 132 + ty * 8 + 4];
        *(float4*)&bf[0] = *(float4*)&kT[d * 132 + tx * 8];
        *(float4*)&bf[4] = *(float4*)&kT[d * 132 + tx * 8 + 4];
#pragma unroll
        for (int i = 0; i < 8; i++)
#pragma unroll
            for (int j = 0; j < 8; j++)
                acc[i][j] = fmaf(af[i], bf[j], acc[i][j]);
    }
#pragma unroll
    for (int ii = 0; ii < 8; ii++) {
        int i = ty * 8 + ii;
#pragma unroll
        for (int jj = 0; jj < 8; jj++) {
            int j = tx * 8 + jj;
            float val = 0.0f;
            if (i >= j) val = acc[ii][jj] * expf(-s * (float)(i - j));
            Ss[i * 129 + j] = val;
        }
    }
    __syncthreads();

    float oc[8][4];
#pragma unroll
    for (int i = 0; i < 8; i++)
#pragma unroll
        for (int j = 0; j < 4; j++) oc[i][j] = 0.0f;

    for (int j = 0; j < 128; j++) {
        float bv[4];
        *(float4*)bv = *(float4*)&vs[j * 68 + tx * 4];
#pragma unroll
        for (int ii = 0; ii < 8; ii++) {
            float a = Ss[(ty * 8 + ii) * 129 + j];
#pragma unroll
            for (int dd = 0; dd < 4; dd++)
                oc[ii][dd] = fmaf(a, bv[dd], oc[ii][dd]);
        }
    }
#pragma unroll
    for (int ii = 0; ii < 8; ii++) {
        float4 o;
        o.x = oc[ii][0]; o.y = oc[ii][1]; o.z = oc[ii][2]; o.w = oc[ii][3];
        *(float4*)(g_o + base + (size_t)(ty * 8 + ii) * Ee + tx * 4) = o;
    }

    float ac[4][4];
#pragma unroll
    for (int i = 0; i < 4; i++)
#pragma unroll
        for (int j = 0; j < 4; j++) ac[i][j] = 0.0f;

    const int dr = ty * 4;
    for (int j = 0; j < 128; j++) {
        float lam = lamk[j];
        float bv[4];
        *(float4*)bv = *(float4*)&vs[j * 68 + tx * 4];
#pragma unroll
        for (int i = 0; i < 4; i++) {
            float a = kT[(dr + i) * 132 + j] * lam;
#pragma unroll
            for (int e2 = 0; e2 < 4; e2++)
                ac[i][e2] = fmaf(a, bv[e2], ac[i][e2]);
        }
    }
    float* Ab = g_A + ((((size_t)b * Hh + h) * NCk + c) * (Dd * Dd));
#pragma unroll
    for (int i = 0; i < 4; i++) {
        float4 o;
        o.x = ac[i][0]; o.y = ac[i][1]; o.z = ac[i][2]; o.w = ac[i][3];
        *(float4*)&Ab[(dr + i) * Dd + tx * 4] = o;
    }
}

// ============================================================
// kv prefix scan: one (b,h,element) chain per thread
// ============================================================
__global__ __launch_bounds__(256) void kv_scan()
{
    const int gidx = blockIdx.x * 256 + threadIdx.x;
    const int bh = gidx >> 12;
    const int e  = gidx & 4095;
    const int h  = bh & 15;
    const float s = head_slope(h);
    const float lamc = expf(-s * (float)Cc);

    size_t off = (size_t)bh * NCk * (Dd * Dd) + e;
    float kv = 0.0f;
#pragma unroll 4
    for (int c = 0; c < NCk; c++) {
        g_kv[off] = kv;
        kv = fmaf(lamc, kv, g_A[off]);
        off += Dd * Dd;
    }
}

// ============================================================
// Inter-chunk: o += lam_q[i] * (q @ kv_prefix)
// ============================================================
#define SMEM_INTER_FLOATS (128*68 + 64*68)

__global__ __launch_bounds__(256) void attn_inter(const float* __restrict__ q)
{
    extern __shared__ float sm[];
    float* qs  = sm;
    float* kvs = sm + 128 * 68;

    const int c = blockIdx.x, h = blockIdx.y, b = blockIdx.z;
    const int tid = threadIdx.x;
    const float s = head_slope(h);
    const size_t base = ((size_t)b * Nn + (size_t)c * Cc) * Ee + (size_t)h * Dd;

#pragma unroll
    for (int t = 0; t < 8; t++) {
        int e = tid + t * 256;
        int row = e >> 4;
        int d4 = (e & 15) * 4;
        *(float4*)&qs[row * 68 + d4] = *(const float4*)(q + base + (size_t)row * Ee + d4);
    }
    const float* kvp = g_kv + (((size_t)b * Hh + h) * NCk + c) * (Dd * Dd);
#pragma unroll
    for (int t = 0; t < 4; t++) {
        int e = tid + t * 256;
        int row = e >> 4;
        int d4 = (e & 15) * 4;
        *(float4*)&kvs[row * 68 + d4] = *(const float4*)(kvp + row * Dd + d4);
    }
    __syncthreads();

    const int tx = tid & 15, ty = tid >> 4;
    float oc[8][4];
#pragma unroll
    for (int i = 0; i < 8; i++)
#pragma unroll
        for (int j = 0; j < 4; j++) oc[i][j] = 0.0f;

    for (int e2 = 0; e2 < 64; e2++) {
        float bv[4];
        *(float4*)bv = *(float4*)&kvs[e2 * 68 + tx * 4];
#pragma unroll
        for (int ii = 0; ii < 8; ii++) {
            float a = qs[(ty * 8 + ii) * 68 + e2];
#pragma unroll
            for (int dd = 0; dd < 4; dd++)
                oc[ii][dd] = fmaf(a, bv[dd], oc[ii][dd]);
        }
    }
#pragma unroll
    for (int ii = 0; ii < 8; ii++) {
        int i = ty * 8 + ii;
        float lamq = expf(-s * (float)(i + 1));
        float* op = g_o + base + (size_t)i * Ee + tx * 4;
        float4 prev = *(float4*)op;
        prev.x = fmaf(lamq, oc[ii][0], prev.x);
        prev.y = fmaf(lamq, oc[ii][1], prev.y);
        prev.z = fmaf(lamq, oc[ii][2], prev.z);
        prev.w = fmaf(lamq, oc[ii][3], prev.w);
        *(float4*)op = prev;
    }
}

// ============================================================
// LayerNorm + sigmoid(gd) * -> g_uh (half, K-PERMUTED)
// ============================================================
__global__ __launch_bounds__(256) void ln_gate(
    const float* __restrict__ gamma, const float* __restrict__ beta)
{
    __shared__ float os[8 * 1024];
    __shared__ float wsum[8], wsq[8];
    __shared__ float mu_s[8], rs_s[8];

    const int tid = threadIdx.x;
    const size_t row0 = (size_t)blockIdx.x * 8;

#pragma unroll
    for (int t = 0; t < 8; t++) {
        int e = tid + t * 256;
        int r = e >> 8;
        int c4 = (e & 255) * 4;
        *(float4*)&os[r * 1024 + c4] = *(const float4*)(g_o + (row0 + r) * 1024 + c4);
    }
    __syncthreads();

    const int lane = tid & 31, wid = tid >> 5;

    for (int r = 0; r < 8; r++) {
        float sum = 0.0f;
#pragma unroll
        for (int t = 0; t < 4; t++) sum += os[r * 1024 + tid + t * 256];
#pragma unroll
        for (int o = 16; o; o >>= 1) sum += __shfl_xor_sync(0xffffffffu, sum, o);
        if (lane == 0) wsum[wid] = sum;
        __syncthreads();
        if (tid == 0) {
            float S = 0.0f;
            for (int w = 0; w < 8; w++) S += wsum[w];
            mu_s[r] = S * (1.0f / 1024.0f);
        }
        __syncthreads();
    }
    for (int r = 0; r < 8; r++) {
        float mu = mu_s[r];
        float sq = 0.0f;
#pragma unroll
        for (int t = 0; t < 4; t++) {
            float d = os[r * 1024 + tid + t * 256] - mu;
            sq = fmaf(d, d, sq);
        }
#pragma unroll
        for (int o = 16; o; o >>= 1) sq += __shfl_xor_sync(0xffffffffu, sq, o);
        if (lane == 0) wsq[wid] = sq;
        __syncthreads();
        if (tid == 0) {
            float Q = 0.0f;
            for (int w = 0; w < 8; w++) Q += wsq[w];
            rs_s[r] = rsqrtf(Q * (1.0f / 1024.0f) + 1e-5f);
        }
        __syncthreads();
    }

    const int r = wid;
    const int cbase = lane * 4;
    const float mu = mu_s[r];
    const float rs = rs_s[r];
#pragma unroll
    for (int t = 0; t < 8; t++) {
        int col = cbase + t * 128;
        float4 ov = *(float4*)&os[r * 1024 + col];
        float4 gd = *(const float4*)(g_gd + (row0 + r) * 1024 + col);
        float4 gm = *(const float4*)(gamma + col);
        float4 bt = *(const float4*)(beta + col);
        float ux = (fmaf((ov.x - mu) * rs, gm.x, bt.x)) * (1.0f / (1.0f + expf(-gd.x)));
        float uy = (fmaf((ov.y - mu) * rs, gm.y, bt.y)) * (1.0f / (1.0f + expf(-gd.y)));
        float uz = (fmaf((ov.z - mu) * rs, gm.z, bt.z)) * (1.0f / (1.0f + expf(-gd.z)));
        float uw = (fmaf((ov.w - mu) * rs, gm.w, bt.w)) * (1.0f / (1.0f + expf(-gd.w)));
        // permuted store: orig uint32 indices col/2, col/2+1
        int o0 = col >> 1;
        size_t rb = (row0 + r) * 512;
        g_uh[rb + knew(o0)]     = packh2(ux, uy);
        g_uh[rb + knew(o0 + 1)] = packh2(uz, uw);
    }
}

// ============================================================
// host launch
// ============================================================
extern "C" void kernel_launch(void* const* d_in, const int* in_sizes, int n_in,
                              void* d_out, int out_size)
{
    const float* x     = (const float*)d_in[0];
    const float* Wq    = (const float*)d_in[1];
    const float* Wk    = (const float*)d_in[2];
    const float* Wv    = (const float*)d_in[3];
    const float* Wo    = (const float*)d_in[4];
    const float* gamma = (const float*)d_in[5];
    const float* beta  = (const float*)d_in[6];
    const float* Wg1   = (const float*)d_in[7];
    const float* Wg2   = (const float*)d_in[8];
    float* out = (float*)d_out;

    static bool init_done = false;
    static float *qp, *kp, *vp;
    if (!init_done) {
        cudaGetSymbolAddress((void**)&qp, g_q);
        cudaGetSymbolAddress((void**)&kp, g_k);
        cudaGetSymbolAddress((void**)&vp, g_v);
        cudaFuncSetAttribute(attn_intra, cudaFuncAttributeMaxDynamicSharedMemorySize,
                             SMEM_INTRA_FLOATS * (int)sizeof(float));
        cudaFuncSetAttribute(attn_inter, cudaFuncAttributeMaxDynamicSharedMemorySize,
                             SMEM_INTER_FLOATS * (int)sizeof(float));
        cudaFuncSetAttribute(gemm_qkv_f16, cudaFuncAttributeMaxDynamicSharedMemorySize,
                             GEMM_SMEM_BIG);
        cudaFuncSetAttribute(gemm_out_f16, cudaFuncAttributeMaxDynamicSharedMemorySize,
                             GEMM_SMEM_BIG);
        cudaFuncSetAttribute(gemm_g1_f16, cudaFuncAttributeMaxDynamicSharedMemorySize,
                             GEMM_SMEM_G1);
        init_done = true;
    }

    const int smem_intra = SMEM_INTRA_FLOATS * (int)sizeof(float);
    const int smem_inter = SMEM_INTER_FLOATS * (int)sizeof(float);

    dim3 blk(256);

    conv_x<<<4096, blk>>>(x);
    conv_wt<<<dim3(32, 32, 4), blk>>>(Wq, Wk, Wv, Wo);
    conv_wg1<<<dim3(2, 32), blk>>>(Wg1);

    gemm_qkv_f16<<<dim3(Ee / 128, Mm / 128, 3), blk, GEMM_SMEM_BIG>>>();
    gemm_g1_f16<<<Mm / 128, blk, GEMM_SMEM_G1>>>();
    sgemm_gd<<<dim3(Ee / 128, Mm / 128), blk>>>(Wg2);

    attn_intra<<<dim3(NCk, Hh, Bb), blk, smem_intra>>>(qp, kp, vp);
    kv_scan<<<512, blk>>>();
    attn_inter<<<dim3(NCk, Hh, Bb), blk, smem_inter>>>(qp);

    ln_gate<<<Mm / 8, blk>>>(gamma, beta);

    gemm_out_f16<<<dim3(Ee / 128, Mm / 128), blk, GEMM_SMEM_BIG>>>(out);
}